// round 14
// baseline (speedup 1.0000x reference)
#include <cuda_runtime.h>
#include <cuda_fp16.h>
#include <math.h>
#include <stdint.h>

// ---------------------------------------------------------------------------
// B=32, N=1024, DIM=512, HEADS=8, HEAD_DIM=64, MLP_HIDDEN=2048. M = 32768.
// fp16 mma.sync; GEMM 8 warps 64x32, k64, 3-stage cp.async.
// Attention: 4 warps x 32 q-rows (two strips sharing K/V fragments),
// fixed-shift softmax, bias in accumulator init, f16x2 exponent.
// ---------------------------------------------------------------------------
#define MROWS 32768
#define DIMC  512
#define HIDC  2048

__device__ float d_x1[MROWS * DIMC];
__device__ __half g_h  [MROWS * DIMC];
__device__ __half g_o  [MROWS * DIMC];
__device__ __half g_hid[MROWS * HIDC];
__device__ __half g_qkv[MROWS * 1536];
__device__ __half g_wqkv[1536 * 512];
__device__ __half g_wprj[512 * 512];
__device__ __half g_w1 [2048 * 512];
__device__ __half g_w2 [512 * 2048];

__device__ __forceinline__ uint32_t smem_u32(const void* p) {
    uint32_t a;
    asm("{ .reg .u64 t; cvta.to.shared.u64 t, %1; cvt.u32.u64 %0, t; }"
        : "=r"(a) : "l"(p));
    return a;
}
__device__ __forceinline__ void ldsm_x4(uint32_t& r0, uint32_t& r1,
                                        uint32_t& r2, uint32_t& r3, uint32_t a) {
    asm volatile("ldmatrix.sync.aligned.m8n8.x4.shared.b16 {%0,%1,%2,%3}, [%4];"
                 : "=r"(r0), "=r"(r1), "=r"(r2), "=r"(r3) : "r"(a));
}
__device__ __forceinline__ void ldsm_x4_t(uint32_t& r0, uint32_t& r1,
                                          uint32_t& r2, uint32_t& r3, uint32_t a) {
    asm volatile("ldmatrix.sync.aligned.m8n8.x4.trans.shared.b16 {%0,%1,%2,%3}, [%4];"
                 : "=r"(r0), "=r"(r1), "=r"(r2), "=r"(r3) : "r"(a));
}
__device__ __forceinline__ void mma_f16(float* d, const uint32_t* a,
                                        uint32_t b0, uint32_t b1) {
    asm volatile("mma.sync.aligned.m16n8k16.row.col.f32.f16.f16.f32 "
                 "{%0,%1,%2,%3}, {%4,%5,%6,%7}, {%8,%9}, {%0,%1,%2,%3};"
                 : "+f"(d[0]), "+f"(d[1]), "+f"(d[2]), "+f"(d[3])
                 : "r"(a[0]), "r"(a[1]), "r"(a[2]), "r"(a[3]), "r"(b0), "r"(b1));
}
__device__ __forceinline__ void cp16(uint32_t s, const void* g) {
    asm volatile("cp.async.cg.shared.global [%0], [%1], 16;" :: "r"(s), "l"(g));
}
__device__ __forceinline__ uint32_t pack2h(float x, float y) {
    __half2 h = __floats2half2_rn(x, y);
    return *(uint32_t*)&h;
}
__device__ __forceinline__ float ex2f(float x) {
    float y;
    asm("ex2.approx.f32 %0, %1;" : "=f"(y) : "f"(x));
    return y;
}
__device__ __forceinline__ uint32_t ex2h2(uint32_t v) {
    uint32_t e;
    asm("ex2.approx.f16x2 %0, %1;" : "=r"(e) : "r"(v));
    return e;
}
__device__ __forceinline__ float gelu1(float u) {
    return 0.5f * u * (1.f + erff(u * 0.70710678118654752f));
}

// ---------------------------------------------------------------------------
// LayerNorm -> fp16
// ---------------------------------------------------------------------------
__global__ void __launch_bounds__(128) ln_h_kernel(
    const float* __restrict__ x, const float* __restrict__ g,
    const float* __restrict__ b, __half* __restrict__ oh)
{
    int row = blockIdx.x, t = threadIdx.x;
    float4 vv = reinterpret_cast<const float4*>(x + (size_t)row * DIMC)[t];
    float s  = vv.x + vv.y + vv.z + vv.w;
    float sq = vv.x*vv.x + vv.y*vv.y + vv.z*vv.z + vv.w*vv.w;
    #pragma unroll
    for (int o = 16; o > 0; o >>= 1) {
        s  += __shfl_xor_sync(0xffffffffu, s,  o);
        sq += __shfl_xor_sync(0xffffffffu, sq, o);
    }
    __shared__ float ss[4], sq2[4];
    int w = t >> 5;
    if ((t & 31) == 0) { ss[w] = s; sq2[w] = sq; }
    __syncthreads();
    s  = ss[0] + ss[1] + ss[2] + ss[3];
    sq = sq2[0] + sq2[1] + sq2[2] + sq2[3];
    float mu  = s * (1.f / DIMC);
    float var = sq * (1.f / DIMC) - mu * mu;
    float inv = rsqrtf(var + 1e-5f);
    float4 gv = reinterpret_cast<const float4*>(g)[t];
    float4 bv = reinterpret_cast<const float4*>(b)[t];
    uint2 u;
    u.x = pack2h((vv.x - mu) * inv * gv.x + bv.x, (vv.y - mu) * inv * gv.y + bv.y);
    u.y = pack2h((vv.z - mu) * inv * gv.z + bv.z, (vv.w - mu) * inv * gv.w + bv.w);
    *(uint2*)(oh + (size_t)row * DIMC + t * 4) = u;
}

// merged fp32->fp16 weight convert
__global__ void __launch_bounds__(256) cvt4_kernel(
    const float* __restrict__ a0, __half* __restrict__ o0,
    const float* __restrict__ a1, __half* __restrict__ o1,
    const float* __restrict__ a2, __half* __restrict__ o2,
    const float* __restrict__ a3, __half* __restrict__ o3)
{
    int i = blockIdx.x * 256 + threadIdx.x;
    const float* src; __half* dst; int off;
    if (i < 196608)      { src = a0; dst = o0; off = i; }
    else if (i < 262144) { src = a1; dst = o1; off = i - 196608; }
    else if (i < 524288) { src = a2; dst = o2; off = i - 262144; }
    else                 { src = a3; dst = o3; off = i - 524288; }
    float4 v = reinterpret_cast<const float4*>(src)[off];
    uint2 u;
    u.x = pack2h(v.x, v.y);
    u.y = pack2h(v.z, v.w);
    *(uint2*)(dst + (size_t)off * 4) = u;
}

// ---------------------------------------------------------------------------
// Warp-MMA fp16 GEMM: 8 warps 64x32 tiles, CTA 128x128, k-chunk 64,
// 3-stage cp.async pipeline, direct epilogue.
// ---------------------------------------------------------------------------
enum { EPI_QKV = 0, EPI_PROJ = 1, EPI_GELU = 2, EPI_OUT = 3 };

#define LDT 72
#define OFF_A 0
#define OFF_B 18432
#define STG   36864
#define GEMM_SMEM (3 * STG)

#define QSCALE 0.1803368801111244f

template<int KTOT, int EPI>
__global__ void __launch_bounds__(256) mma_gemm(
    const __half* __restrict__ A, const __half* __restrict__ B,
    const float* __restrict__ bias, const float* __restrict__ resid,
    float* __restrict__ out0, __half* __restrict__ oh, int N)
{
    extern __shared__ __align__(128) char dsm[];
    uint32_t sb = smem_u32(dsm);
    int t = threadIdx.x, wid = t >> 5, lane = t & 31;
    int m0 = blockIdx.y << 7, n0 = blockIdx.x << 7;
    int warp_m = wid & 1, warp_n = wid >> 1;

    float acc[4][4][4];
    #pragma unroll
    for (int i = 0; i < 4; i++)
        #pragma unroll
        for (int j = 0; j < 4; j++)
            #pragma unroll
            for (int r = 0; r < 4; r++) acc[i][j][r] = 0.f;

    int lrow = lane & 15, lcb = (lane >> 4) << 3;
    const int NCH = KTOT / 64;

    auto issue = [&](int stg, int k0) {
        #pragma unroll
        for (int i = t; i < 1024; i += 256) {
            int r = i >> 3, q = i & 7;
            size_t ga = (size_t)(m0 + r) * KTOT + k0 + q * 8;
            size_t gb = (size_t)(n0 + r) * KTOT + k0 + q * 8;
            uint32_t off = (uint32_t)stg * STG + (uint32_t)(r * LDT + q * 8) * 2;
            cp16(sb + off + OFF_A, A + ga);
            cp16(sb + off + OFF_B, B + gb);
        }
        asm volatile("cp.async.commit_group;" ::: "memory");
    };

    issue(0, 0);
    issue(1, 64);
    #pragma unroll 1
    for (int ch = 0; ch < NCH; ch++) {
        if (ch + 1 < NCH)
            asm volatile("cp.async.wait_group 1;" ::: "memory");
        else
            asm volatile("cp.async.wait_group 0;" ::: "memory");
        __syncthreads();
        uint32_t stb = sb + (uint32_t)(ch % 3) * STG;
        #pragma unroll
        for (int k16 = 0; k16 < 4; k16++) {
            uint32_t af[4][4], bf[2][4];
            int col = k16 * 16 + lcb;
            #pragma unroll
            for (int am = 0; am < 4; am++) {
                uint32_t off = (uint32_t)((warp_m * 64 + am * 16 + lrow) * LDT + col) * 2;
                ldsm_x4(af[am][0], af[am][1], af[am][2], af[am][3], stb + OFF_A + off);
            }
            #pragma unroll
            for (int an2 = 0; an2 < 2; an2++) {
                uint32_t off = (uint32_t)((warp_n * 32 + an2 * 16 + lrow) * LDT + col) * 2;
                ldsm_x4(bf[an2][0], bf[an2][1], bf[an2][2], bf[an2][3], stb + OFF_B + off);
            }
            #pragma unroll
            for (int am = 0; am < 4; am++)
                #pragma unroll
                for (int an = 0; an < 4; an++) {
                    int a2 = an >> 1, p = an & 1;
                    mma_f16(acc[am][an], af[am], bf[a2][p], bf[a2][p + 2]);
                }
        }
        if (ch + 2 < NCH) issue((ch + 2) % 3, (ch + 2) * 64);
    }

    int rbase = m0 + warp_m * 64 + (lane >> 2);
    int cbase = n0 + warp_n * 32 + (lane & 3) * 2;

    if (EPI == EPI_QKV) {
        float sc = (n0 < 512) ? QSCALE : 1.f;
        #pragma unroll
        for (int am = 0; am < 4; am++) {
            #pragma unroll
            for (int an = 0; an < 4; an++) {
                int n = cbase + an * 8;
                #pragma unroll
                for (int h2 = 0; h2 < 2; h2++) {
                    int m = rbase + am * 16 + h2 * 8;
                    *(uint32_t*)(oh + (size_t)m * 1536 + n) =
                        pack2h(acc[am][an][2 * h2] * sc, acc[am][an][2 * h2 + 1] * sc);
                }
            }
        }
    } else if (EPI == EPI_GELU) {
        float2 bv[4];
        #pragma unroll
        for (int an = 0; an < 4; an++)
            bv[an] = *(const float2*)(bias + cbase + an * 8);
        #pragma unroll
        for (int am = 0; am < 4; am++) {
            #pragma unroll
            for (int an = 0; an < 4; an++) {
                int n = cbase + an * 8;
                #pragma unroll
                for (int h2 = 0; h2 < 2; h2++) {
                    int m = rbase + am * 16 + h2 * 8;
                    float g0 = gelu1(acc[am][an][2 * h2]     + bv[an].x);
                    float g1 = gelu1(acc[am][an][2 * h2 + 1] + bv[an].y);
                    *(uint32_t*)(oh + (size_t)m * HIDC + n) = pack2h(g0, g1);
                }
            }
        }
    } else {
        float2 bv[4];
        #pragma unroll
        for (int an = 0; an < 4; an++)
            bv[an] = *(const float2*)(bias + cbase + an * 8);
        #pragma unroll
        for (int am = 0; am < 4; am++) {
            #pragma unroll
            for (int an = 0; an < 4; an++) {
                int n = cbase + an * 8;
                #pragma unroll
                for (int h2 = 0; h2 < 2; h2++) {
                    int m = rbase + am * 16 + h2 * 8;
                    float2 rv = *(const float2*)(resid + (size_t)m * N + n);
                    float2 o2;
                    o2.x = rv.x + acc[am][an][2 * h2]     + bv[an].x;
                    o2.y = rv.y + acc[am][an][2 * h2 + 1] + bv[an].y;
                    *(float2*)(out0 + (size_t)m * N + n) = o2;
                }
            }
        }
    }
}

// ---------------------------------------------------------------------------
// fp16 flash attention: 4 warps x 32 q-rows (two 16-row strips sharing K/V
// fragments), fixed-shift softmax, bias in accum init, f16x2 exponent.
// ---------------------------------------------------------------------------
#define A_Q  0u
#define A_KV 18432u
#define KV_STG 18432u
#define A_BT 92160u
#define A_LI 93184u
#define ATTN_SMEM 93696
#define LOG2E 1.4426950408889634f
#define BSHIFT (4.0f * LOG2E)

__global__ void __launch_bounds__(128) attn_tc_kernel(
    const __half* __restrict__ qkv_g, const float* __restrict__ btab_g,
    __half* __restrict__ o_g)
{
    extern __shared__ char sm_[];
    __half* sq = (__half*)(sm_ + A_Q);
    float* btab = (float*)(sm_ + A_BT);
    float* linv = (float*)(sm_ + A_LI);
    uint32_t sb = smem_u32(sm_);

    int qb = blockIdx.x, bh = blockIdx.y;
    int hh = bh & 7, bb = bh >> 3;
    int t = threadIdx.x, wid = t >> 5, lane = t & 31;
    int lrow = lane & 15, lcb = (lane >> 4) << 3;

    const __half* qsec = qkv_g + (size_t)bb * 1024 * 1536 + hh * 64;
    const __half* ksec = qsec + 512;
    const __half* vsec = qsec + 1024;

    auto issueKV = [&](int kt) {
        uint32_t base = sb + A_KV + (uint32_t)(kt & 3) * KV_STG;
        #pragma unroll
        for (int i = t; i < 512; i += 128) {
            int r = i >> 3, c8 = (i & 7) * 8;
            size_t row = (size_t)(kt * 64 + r) * 1536;
            uint32_t off = (uint32_t)(r * 72 + c8) * 2;
            cp16(base + off, ksec + row + c8);
            cp16(base + 9216 + off, vsec + row + c8);
        }
        asm volatile("cp.async.commit_group;" ::: "memory");
    };

    for (int i = t; i < 225; i += 128)
        btab[i] = btab_g[i * 8 + hh] * LOG2E - BSHIFT;
    for (int i = t; i < 1024; i += 128) {
        int r = i >> 3, c8 = (i & 7) * 8;
        *(uint4*)(sq + r * 72 + c8) =
            *(const uint4*)(qsec + (size_t)(qb * 128 + r) * 1536 + c8);
    }
    issueKV(0);
    issueKV(1);
    issueKV(2);
    __syncthreads();
    float cb = btab[224];
    // two strips per warp: rows wid*32 + s*16
    uint32_t qf[2][4][4];
    #pragma unroll
    for (int s = 0; s < 2; s++)
        #pragma unroll
        for (int k = 0; k < 4; k++) {
            uint32_t off = (uint32_t)((wid * 32 + s * 16 + lrow) * 72 + k * 16 + lcb) * 2;
            ldsm_x4(qf[s][k][0], qf[s][k][1], qf[s][k][2], qf[s][k][3], sb + A_Q + off);
        }

    float oacc[2][8][4];
    #pragma unroll
    for (int s = 0; s < 2; s++)
        #pragma unroll
        for (int j = 0; j < 8; j++)
            #pragma unroll
            for (int r = 0; r < 4; r++) oacc[s][j][r] = 0.f;
    float lsum[2][2] = {{0.f, 0.f}, {0.f, 0.f}};
    int q2 = (lane & 3) * 2;
    int tr0 = qb * 128 + wid * 32 + (lane >> 2);
    // per strip, per h: query coords
    int qys[2][2], qxs[2][2];
    #pragma unroll
    for (int s = 0; s < 2; s++) {
        int r0 = tr0 + s * 16;
        qys[s][0] = r0 >> 5;       qxs[s][0] = r0 & 31;
        qys[s][1] = (r0 + 8) >> 5; qxs[s][1] = (r0 + 8) & 31;
    }

    #pragma unroll 1
    for (int kt = 0; kt < 16; kt++) {
        int rem = 15 - kt;
        if (rem >= 2)      asm volatile("cp.async.wait_group 2;" ::: "memory");
        else if (rem == 1) asm volatile("cp.async.wait_group 1;" ::: "memory");
        else               asm volatile("cp.async.wait_group 0;" ::: "memory");
        __syncthreads();
        uint32_t kbase = sb + A_KV + (uint32_t)(kt & 3) * KV_STG;
        uint32_t vbase = kbase + 9216;

        // K fragments loaded ONCE for both strips
        uint32_t bk[4][4];
        #pragma unroll
        for (int g = 0; g < 4; g++) {
            uint32_t off = (uint32_t)((g * 16 + lrow) * 72 + 0 * 16 + lcb) * 2;
            (void)off;
        }

        uint32_t ap[2][4][4];
        #pragma unroll
        for (int k = 0; k < 4; k++) {
            // load K fragment for this k16 once, use for both strips
            uint32_t bkk[4][4];
            #pragma unroll
            for (int g = 0; g < 4; g++) {
                uint32_t off = (uint32_t)((g * 16 + lrow) * 72 + k * 16 + lcb) * 2;
                ldsm_x4(bkk[g][0], bkk[g][1], bkk[g][2], bkk[g][3], kbase + off);
            }
            #pragma unroll
            for (int g = 0; g < 4; g++) {
                bk[g][0] = bkk[g][0]; bk[g][1] = bkk[g][1];
                bk[g][2] = bkk[g][2]; bk[g][3] = bkk[g][3];
            }
            // stash per-k fragments is register-heavy; instead run both strips
            // inside the k-loop on partial accumulators kept per strip.
            if (k == 0) {
                // initialize strip accumulators lazily on first k
            }
            // handled below via per-strip sacc arrays
            (void)ap;
            break;
        }

        // Recompute structure: per-strip sacc, K loaded per k16 once.
        float sacc0[8][4], sacc1[8][4];
        bool f00 = (2 * kt + 1) < qys[0][0] + 28;
        bool f01 = (2 * kt + 1) < qys[0][1] + 28;
        bool f10 = (2 * kt + 1) < qys[1][0] + 28;
        bool f11 = (2 * kt + 1) < qys[1][1] + 28;
        {
            float a0 = f00 ? cb : 0.f, a1 = f01 ? cb : 0.f;
            float b0 = f10 ? cb : 0.f, b1 = f11 ? cb : 0.f;
            #pragma unroll
            for (int j = 0; j < 8; j++) {
                sacc0[j][0] = a0; sacc0[j][1] = a0;
                sacc0[j][2] = a1; sacc0[j][3] = a1;
                sacc1[j][0] = b0; sacc1[j][1] = b0;
                sacc1[j][2] = b1; sacc1[j][3] = b1;
            }
        }
        #pragma unroll
        for (int k = 0; k < 4; k++) {
            uint32_t bkk[4][4];
            #pragma unroll
            for (int g = 0; g < 4; g++) {
                uint32_t off = (uint32_t)((g * 16 + lrow) * 72 + k * 16 + lcb) * 2;
                ldsm_x4(bkk[g][0], bkk[g][1], bkk[g][2], bkk[g][3], kbase + off);
            }
            #pragma unroll
            for (int j = 0; j < 8; j++) {
                int g = j >> 1, p = j & 1;
                mma_f16(sacc0[j], qf[0][k], bkk[g][p], bkk[g][p + 2]);
                mma_f16(sacc1[j], qf[1][k], bkk[g][p], bkk[g][p + 2]);
            }
        }

        // exponent per strip
        uint32_t ap0[8][2], ap1[8][2];
        #pragma unroll
        for (int s = 0; s < 2; s++) {
            float (*sa)[4] = s ? sacc1 : sacc0;
            uint32_t (*apx)[2] = s ? ap1 : ap0;
            #pragma unroll
            for (int h = 0; h < 2; h++) {
                bool fast = s ? (h ? f11 : f10) : (h ? f01 : f00);
                if (fast) {
                    __half2 accs = __floats2half2_rn(0.f, 0.f);
                    #pragma unroll
                    for (int j = 0; j < 8; j++) {
                        uint32_t e = ex2h2(pack2h(sa[j][h * 2], sa[j][h * 2 + 1]));
                        apx[j][h] = e;
                        accs = __hadd2(accs, *(__half2*)&e);
                    }
                    float2 f = __half22float2(accs);
                    lsum[s][h] += f.x + f.y;
                } else {
                    int qy = qys[s][h], qx = qxs[s][h];
                    int be = (qy - 2 * kt + 31) * 63 + qx + 31;
                    int bo = be - 63;
                    float sum = 0.f;
                    #pragma unroll
                    for (int j = 0; j < 8; j++) {
                        int id0 = ((j < 4) ? be : bo) - ((j & 3) * 8 + q2);
                        int i0 = id0 < 224 ? id0 : 224;
                        int i1 = id0 - 1 < 224 ? id0 - 1 : 224;
                        float e0 = ex2f(sa[j][h * 2 + 0] + btab[i0]);
                        float e1 = ex2f(sa[j][h * 2 + 1] + btab[i1]);
                        apx[j][h] = pack2h(e0, e1);
                        sum += e0 + e1;
                    }
                    lsum[s][h] += sum;
                }
            }
        }

        // O += P V with V fragments loaded ONCE for both strips
        #pragma unroll
        for (int k = 0; k < 4; k++) {
            uint32_t bv[4][4];
            #pragma unroll
            for (int g = 0; g < 4; g++) {
                uint32_t off = (uint32_t)((k * 16 + lrow) * 72 + g * 16 + lcb) * 2;
                ldsm_x4_t(bv[g][0], bv[g][1], bv[g][2], bv[g][3], vbase + off);
            }
            uint32_t a0[4] = {ap0[2*k][0], ap0[2*k][1], ap0[2*k+1][0], ap0[2*k+1][1]};
            uint32_t a1[4] = {ap1[2*k][0], ap1[2*k][1], ap1[2*k+1][0], ap1[2*k+1][1]};
            #pragma unroll
            for (int j = 0; j < 8; j++) {
                int g = j >> 1, p = j & 1;
                mma_f16(oacc[0][j], a0, bv[g][p * 2], bv[g][p * 2 + 1]);
                mma_f16(oacc[1][j], a1, bv[g][p * 2], bv[g][p * 2 + 1]);
            }
        }
        if (kt + 3 < 16) issueKV(kt + 3);
    }

    #pragma unroll
    for (int s = 0; s < 2; s++)
        #pragma unroll
        for (int h = 0; h < 2; h++) {
            lsum[s][h] += __shfl_xor_sync(0xffffffffu, lsum[s][h], 1);
            lsum[s][h] += __shfl_xor_sync(0xffffffffu, lsum[s][h], 2);
        }
    if ((lane & 3) == 0) {
        #pragma unroll
        for (int s = 0; s < 2; s++) {
            linv[wid * 32 + s * 16 + (lane >> 2)]     = 1.f / lsum[s][0];
            linv[wid * 32 + s * 16 + (lane >> 2) + 8] = 1.f / lsum[s][1];
        }
    }
    __syncthreads();
    float* ow = (float*)sm_ + wid * 16 * 66;
    #pragma unroll 1
    for (int s = 0; s < 2; s++) {
        #pragma unroll
        for (int j = 0; j < 8; j++) {
            int c = j * 8 + (lane & 3) * 2;
            int r = lane >> 2;
            ow[r * 66 + c]           = oacc[s][j][0];
            ow[r * 66 + c + 1]       = oacc[s][j][1];
            ow[(r + 8) * 66 + c]     = oacc[s][j][2];
            ow[(r + 8) * 66 + c + 1] = oacc[s][j][3];
        }
        __syncwarp();
        for (int i = lane; i < 256; i += 32) {
            int r = i >> 4, cg = (i & 15) * 4;
            float inv = linv[wid * 32 + s * 16 + r];
            uint2 u;
            u.x = pack2h(ow[r * 66 + cg] * inv,     ow[r * 66 + cg + 1] * inv);
            u.y = pack2h(ow[r * 66 + cg + 2] * inv, ow[r * 66 + cg + 3] * inv);
            size_t go = ((size_t)bb * 1024 + qb * 128 + wid * 32 + s * 16 + r) * 512
                        + hh * 64 + cg;
            *(uint2*)(o_g + go) = u;
        }
        __syncwarp();
    }
}

// ---------------------------------------------------------------------------
// Launcher
// ---------------------------------------------------------------------------
extern "C" void kernel_launch(void* const* d_in, const int* in_sizes, int n_in,
                              void* d_out, int out_size)
{
    const float* x      = (const float*)d_in[0];
    const float* qkv_w  = (const float*)d_in[1];
    const float* proj_w = (const float*)d_in[2];
    const float* proj_b = (const float*)d_in[3];
    const float* mlp_w1 = (const float*)d_in[4];
    const float* mlp_b1 = (const float*)d_in[5];
    const float* mlp_w2 = (const float*)d_in[6];
    const float* mlp_b2 = (const float*)d_in[7];
    const float* n1g    = (const float*)d_in[8];
    const float* n1b    = (const float*)d_in[9];
    const float* n2g    = (const float*)d_in[10];
    const float* n2b    = (const float*)d_in[11];
    const float* btab   = (const float*)d_in[12];
    float* out = (float*)d_out;

    float* x1;
    cudaGetSymbolAddress((void**)&x1, d_x1);
    __half *h_, *o_, *hid, *qkv, *wq, *wp, *w1, *w2;
    cudaGetSymbolAddress((void**)&h_,  g_h);
    cudaGetSymbolAddress((void**)&o_,  g_o);
    cudaGetSymbolAddress((void**)&hid, g_hid);
    cudaGetSymbolAddress((void**)&qkv, g_qkv);
    cudaGetSymbolAddress((void**)&wq,  g_wqkv);
    cudaGetSymbolAddress((void**)&wp,  g_wprj);
    cudaGetSymbolAddress((void**)&w1,  g_w1);
    cudaGetSymbolAddress((void**)&w2,  g_w2);

    cudaFuncSetAttribute(attn_tc_kernel,
        cudaFuncAttributeMaxDynamicSharedMemorySize, ATTN_SMEM);
    cudaFuncSetAttribute(mma_gemm<512, EPI_QKV>,
        cudaFuncAttributeMaxDynamicSharedMemorySize, GEMM_SMEM);
    cudaFuncSetAttribute(mma_gemm<512, EPI_PROJ>,
        cudaFuncAttributeMaxDynamicSharedMemorySize, GEMM_SMEM);
    cudaFuncSetAttribute(mma_gemm<512, EPI_GELU>,
        cudaFuncAttributeMaxDynamicSharedMemorySize, GEMM_SMEM);
    cudaFuncSetAttribute(mma_gemm<2048, EPI_OUT>,
        cudaFuncAttributeMaxDynamicSharedMemorySize, GEMM_SMEM);

    cvt4_kernel<<<3072, 256>>>(qkv_w, wq, proj_w, wp, mlp_w1, w1, mlp_w2, w2);

    // LN1
    ln_h_kernel<<<MROWS, 128>>>(x, n1g, n1b, h_);
    // QKV (N=1536)
    mma_gemm<512, EPI_QKV><<<dim3(12, 256), 256, GEMM_SMEM>>>(
        h_, wq, nullptr, nullptr, nullptr, qkv, 1536);
    // attention (128 threads, 4 warps x 32 rows)
    attn_tc_kernel<<<dim3(8, 256), 128, ATTN_SMEM>>>(qkv, btab, o_);
    // proj + residual (N=512)
    mma_gemm<512, EPI_PROJ><<<dim3(4, 256), 256, GEMM_SMEM>>>(
        o_, wp, proj_b, x, x1, nullptr, 512);
    // LN2
    ln_h_kernel<<<MROWS, 128>>>(x1, n2g, n2b, h_);
    // MLP1 + GELU (N=2048)
    mma_gemm<512, EPI_GELU><<<dim3(16, 256), 256, GEMM_SMEM>>>(
        h_, w1, mlp_b1, nullptr, nullptr, hid, 2048);
    // MLP2 + residual -> out (N=512, K=2048)
    mma_gemm<2048, EPI_OUT><<<dim3(4, 256), 256, GEMM_SMEM>>>(
        hid, w2, mlp_b2, x1, out, nullptr, 512);
}

// round 15
// speedup vs baseline: 1.0957x; 1.0957x over previous
#include <cuda_runtime.h>
#include <cuda_fp16.h>
#include <math.h>
#include <stdint.h>

// ---------------------------------------------------------------------------
// B=32, N=1024, DIM=512, HEADS=8, HEAD_DIM=64, MLP_HIDDEN=2048. M = 32768.
// fp16 mma.sync; GEMM 8 warps 64x32, k64, 3-stage cp.async.
// Attention (R12 config): 8 warps x 16 q-rows, fixed-shift softmax, bias in
// accumulator init, f16x2 exponent. LN processes 2 rows per 256-thr block.
// ---------------------------------------------------------------------------
#define MROWS 32768
#define DIMC  512
#define HIDC  2048

__device__ float d_x1[MROWS * DIMC];
__device__ __half g_h  [MROWS * DIMC];
__device__ __half g_o  [MROWS * DIMC];
__device__ __half g_hid[MROWS * HIDC];
__device__ __half g_qkv[MROWS * 1536];
__device__ __half g_wqkv[1536 * 512];
__device__ __half g_wprj[512 * 512];
__device__ __half g_w1 [2048 * 512];
__device__ __half g_w2 [512 * 2048];

__device__ __forceinline__ uint32_t smem_u32(const void* p) {
    uint32_t a;
    asm("{ .reg .u64 t; cvta.to.shared.u64 t, %1; cvt.u32.u64 %0, t; }"
        : "=r"(a) : "l"(p));
    return a;
}
__device__ __forceinline__ void ldsm_x4(uint32_t& r0, uint32_t& r1,
                                        uint32_t& r2, uint32_t& r3, uint32_t a) {
    asm volatile("ldmatrix.sync.aligned.m8n8.x4.shared.b16 {%0,%1,%2,%3}, [%4];"
                 : "=r"(r0), "=r"(r1), "=r"(r2), "=r"(r3) : "r"(a));
}
__device__ __forceinline__ void ldsm_x4_t(uint32_t& r0, uint32_t& r1,
                                          uint32_t& r2, uint32_t& r3, uint32_t a) {
    asm volatile("ldmatrix.sync.aligned.m8n8.x4.trans.shared.b16 {%0,%1,%2,%3}, [%4];"
                 : "=r"(r0), "=r"(r1), "=r"(r2), "=r"(r3) : "r"(a));
}
__device__ __forceinline__ void mma_f16(float* d, const uint32_t* a,
                                        uint32_t b0, uint32_t b1) {
    asm volatile("mma.sync.aligned.m16n8k16.row.col.f32.f16.f16.f32 "
                 "{%0,%1,%2,%3}, {%4,%5,%6,%7}, {%8,%9}, {%0,%1,%2,%3};"
                 : "+f"(d[0]), "+f"(d[1]), "+f"(d[2]), "+f"(d[3])
                 : "r"(a[0]), "r"(a[1]), "r"(a[2]), "r"(a[3]), "r"(b0), "r"(b1));
}
__device__ __forceinline__ void cp16(uint32_t s, const void* g) {
    asm volatile("cp.async.cg.shared.global [%0], [%1], 16;" :: "r"(s), "l"(g));
}
__device__ __forceinline__ uint32_t pack2h(float x, float y) {
    __half2 h = __floats2half2_rn(x, y);
    return *(uint32_t*)&h;
}
__device__ __forceinline__ float ex2f(float x) {
    float y;
    asm("ex2.approx.f32 %0, %1;" : "=f"(y) : "f"(x));
    return y;
}
__device__ __forceinline__ uint32_t ex2h2(uint32_t v) {
    uint32_t e;
    asm("ex2.approx.f16x2 %0, %1;" : "=r"(e) : "r"(v));
    return e;
}
__device__ __forceinline__ float gelu1(float u) {
    return 0.5f * u * (1.f + erff(u * 0.70710678118654752f));
}

// ---------------------------------------------------------------------------
// LayerNorm -> fp16 : 2 rows per 256-thread block (warp-quad per row half)
// ---------------------------------------------------------------------------
__global__ void __launch_bounds__(256) ln_h_kernel(
    const float* __restrict__ x, const float* __restrict__ g,
    const float* __restrict__ b, __half* __restrict__ oh)
{
    int sub = threadIdx.x >> 7;            // 0 or 1: which row
    int row = blockIdx.x * 2 + sub;
    int t = threadIdx.x & 127;
    float4 vv = reinterpret_cast<const float4*>(x + (size_t)row * DIMC)[t];
    float s  = vv.x + vv.y + vv.z + vv.w;
    float sq = vv.x*vv.x + vv.y*vv.y + vv.z*vv.z + vv.w*vv.w;
    #pragma unroll
    for (int o = 16; o > 0; o >>= 1) {
        s  += __shfl_xor_sync(0xffffffffu, s,  o);
        sq += __shfl_xor_sync(0xffffffffu, sq, o);
    }
    __shared__ float ss[8], sq2[8];
    int w = threadIdx.x >> 5;
    if ((t & 31) == 0) { ss[w] = s; sq2[w] = sq; }
    __syncthreads();
    int wb = sub * 4;
    s  = ss[wb] + ss[wb+1] + ss[wb+2] + ss[wb+3];
    sq = sq2[wb] + sq2[wb+1] + sq2[wb+2] + sq2[wb+3];
    float mu  = s * (1.f / DIMC);
    float var = sq * (1.f / DIMC) - mu * mu;
    float inv = rsqrtf(var + 1e-5f);
    float4 gv = reinterpret_cast<const float4*>(g)[t];
    float4 bv = reinterpret_cast<const float4*>(b)[t];
    uint2 u;
    u.x = pack2h((vv.x - mu) * inv * gv.x + bv.x, (vv.y - mu) * inv * gv.y + bv.y);
    u.y = pack2h((vv.z - mu) * inv * gv.z + bv.z, (vv.w - mu) * inv * gv.w + bv.w);
    *(uint2*)(oh + (size_t)row * DIMC + t * 4) = u;
}

// merged fp32->fp16 weight convert
__global__ void __launch_bounds__(256) cvt4_kernel(
    const float* __restrict__ a0, __half* __restrict__ o0,
    const float* __restrict__ a1, __half* __restrict__ o1,
    const float* __restrict__ a2, __half* __restrict__ o2,
    const float* __restrict__ a3, __half* __restrict__ o3)
{
    int i = blockIdx.x * 256 + threadIdx.x;
    const float* src; __half* dst; int off;
    if (i < 196608)      { src = a0; dst = o0; off = i; }
    else if (i < 262144) { src = a1; dst = o1; off = i - 196608; }
    else if (i < 524288) { src = a2; dst = o2; off = i - 262144; }
    else                 { src = a3; dst = o3; off = i - 524288; }
    float4 v = reinterpret_cast<const float4*>(src)[off];
    uint2 u;
    u.x = pack2h(v.x, v.y);
    u.y = pack2h(v.z, v.w);
    *(uint2*)(dst + (size_t)off * 4) = u;
}

// ---------------------------------------------------------------------------
// Warp-MMA fp16 GEMM: 8 warps 64x32 tiles, CTA 128x128, k-chunk 64,
// 3-stage cp.async pipeline, direct epilogue.
// ---------------------------------------------------------------------------
enum { EPI_QKV = 0, EPI_PROJ = 1, EPI_GELU = 2, EPI_OUT = 3 };

#define LDT 72
#define OFF_A 0
#define OFF_B 18432
#define STG   36864
#define GEMM_SMEM (3 * STG)

#define QSCALE 0.1803368801111244f

template<int KTOT, int EPI>
__global__ void __launch_bounds__(256) mma_gemm(
    const __half* __restrict__ A, const __half* __restrict__ B,
    const float* __restrict__ bias, const float* __restrict__ resid,
    float* __restrict__ out0, __half* __restrict__ oh, int N)
{
    extern __shared__ __align__(128) char dsm[];
    uint32_t sb = smem_u32(dsm);
    int t = threadIdx.x, wid = t >> 5, lane = t & 31;
    int m0 = blockIdx.y << 7, n0 = blockIdx.x << 7;
    int warp_m = wid & 1, warp_n = wid >> 1;

    float acc[4][4][4];
    #pragma unroll
    for (int i = 0; i < 4; i++)
        #pragma unroll
        for (int j = 0; j < 4; j++)
            #pragma unroll
            for (int r = 0; r < 4; r++) acc[i][j][r] = 0.f;

    int lrow = lane & 15, lcb = (lane >> 4) << 3;
    const int NCH = KTOT / 64;

    auto issue = [&](int stg, int k0) {
        #pragma unroll
        for (int i = t; i < 1024; i += 256) {
            int r = i >> 3, q = i & 7;
            size_t ga = (size_t)(m0 + r) * KTOT + k0 + q * 8;
            size_t gb = (size_t)(n0 + r) * KTOT + k0 + q * 8;
            uint32_t off = (uint32_t)stg * STG + (uint32_t)(r * LDT + q * 8) * 2;
            cp16(sb + off + OFF_A, A + ga);
            cp16(sb + off + OFF_B, B + gb);
        }
        asm volatile("cp.async.commit_group;" ::: "memory");
    };

    issue(0, 0);
    issue(1, 64);
    #pragma unroll 1
    for (int ch = 0; ch < NCH; ch++) {
        if (ch + 1 < NCH)
            asm volatile("cp.async.wait_group 1;" ::: "memory");
        else
            asm volatile("cp.async.wait_group 0;" ::: "memory");
        __syncthreads();
        uint32_t stb = sb + (uint32_t)(ch % 3) * STG;
        #pragma unroll
        for (int k16 = 0; k16 < 4; k16++) {
            uint32_t af[4][4], bf[2][4];
            int col = k16 * 16 + lcb;
            #pragma unroll
            for (int am = 0; am < 4; am++) {
                uint32_t off = (uint32_t)((warp_m * 64 + am * 16 + lrow) * LDT + col) * 2;
                ldsm_x4(af[am][0], af[am][1], af[am][2], af[am][3], stb + OFF_A + off);
            }
            #pragma unroll
            for (int an2 = 0; an2 < 2; an2++) {
                uint32_t off = (uint32_t)((warp_n * 32 + an2 * 16 + lrow) * LDT + col) * 2;
                ldsm_x4(bf[an2][0], bf[an2][1], bf[an2][2], bf[an2][3], stb + OFF_B + off);
            }
            #pragma unroll
            for (int am = 0; am < 4; am++)
                #pragma unroll
                for (int an = 0; an < 4; an++) {
                    int a2 = an >> 1, p = an & 1;
                    mma_f16(acc[am][an], af[am], bf[a2][p], bf[a2][p + 2]);
                }
        }
        if (ch + 2 < NCH) issue((ch + 2) % 3, (ch + 2) * 64);
    }

    int rbase = m0 + warp_m * 64 + (lane >> 2);
    int cbase = n0 + warp_n * 32 + (lane & 3) * 2;

    if (EPI == EPI_QKV) {
        float sc = (n0 < 512) ? QSCALE : 1.f;
        #pragma unroll
        for (int am = 0; am < 4; am++) {
            #pragma unroll
            for (int an = 0; an < 4; an++) {
                int n = cbase + an * 8;
                #pragma unroll
                for (int h2 = 0; h2 < 2; h2++) {
                    int m = rbase + am * 16 + h2 * 8;
                    *(uint32_t*)(oh + (size_t)m * 1536 + n) =
                        pack2h(acc[am][an][2 * h2] * sc, acc[am][an][2 * h2 + 1] * sc);
                }
            }
        }
    } else if (EPI == EPI_GELU) {
        float2 bv[4];
        #pragma unroll
        for (int an = 0; an < 4; an++)
            bv[an] = *(const float2*)(bias + cbase + an * 8);
        #pragma unroll
        for (int am = 0; am < 4; am++) {
            #pragma unroll
            for (int an = 0; an < 4; an++) {
                int n = cbase + an * 8;
                #pragma unroll
                for (int h2 = 0; h2 < 2; h2++) {
                    int m = rbase + am * 16 + h2 * 8;
                    float g0 = gelu1(acc[am][an][2 * h2]     + bv[an].x);
                    float g1 = gelu1(acc[am][an][2 * h2 + 1] + bv[an].y);
                    *(uint32_t*)(oh + (size_t)m * HIDC + n) = pack2h(g0, g1);
                }
            }
        }
    } else {   // EPI_PROJ / EPI_OUT: fp32 out = resid + c + bias
        float2 bv[4];
        #pragma unroll
        for (int an = 0; an < 4; an++)
            bv[an] = *(const float2*)(bias + cbase + an * 8);
        #pragma unroll
        for (int am = 0; am < 4; am++) {
            #pragma unroll
            for (int an = 0; an < 4; an++) {
                int n = cbase + an * 8;
                #pragma unroll
                for (int h2 = 0; h2 < 2; h2++) {
                    int m = rbase + am * 16 + h2 * 8;
                    float2 rv = *(const float2*)(resid + (size_t)m * N + n);
                    float2 o2;
                    o2.x = rv.x + acc[am][an][2 * h2]     + bv[an].x;
                    o2.y = rv.y + acc[am][an][2 * h2 + 1] + bv[an].y;
                    *(float2*)(out0 + (size_t)m * N + n) = o2;
                }
            }
        }
    }
}

// ---------------------------------------------------------------------------
// fp16 tensor-core flash attention (R12 config): fixed-shift softmax, bias in
// accumulator init on fast path, f16x2 exponent.
// ---------------------------------------------------------------------------
#define A_Q  0u
#define A_KV 18432u
#define KV_STG 18432u
#define A_BT 92160u
#define A_LI 93184u
#define ATTN_SMEM 93696
#define LOG2E 1.4426950408889634f
#define BSHIFT (4.0f * LOG2E)

__global__ void __launch_bounds__(256) attn_tc_kernel(
    const __half* __restrict__ qkv_g, const float* __restrict__ btab_g,
    __half* __restrict__ o_g)
{
    extern __shared__ char sm_[];
    __half* sq = (__half*)(sm_ + A_Q);
    float* btab = (float*)(sm_ + A_BT);
    float* linv = (float*)(sm_ + A_LI);
    uint32_t sb = smem_u32(sm_);

    int qb = blockIdx.x, bh = blockIdx.y;
    int hh = bh & 7, bb = bh >> 3;
    int t = threadIdx.x, wid = t >> 5, lane = t & 31;
    int lrow = lane & 15, lcb = (lane >> 4) << 3;

    const __half* qsec = qkv_g + (size_t)bb * 1024 * 1536 + hh * 64;
    const __half* ksec = qsec + 512;
    const __half* vsec = qsec + 1024;

    auto issueKV = [&](int kt) {
        uint32_t base = sb + A_KV + (uint32_t)(kt & 3) * KV_STG;
        #pragma unroll
        for (int i = t; i < 512; i += 256) {
            int r = i >> 3, c8 = (i & 7) * 8;
            size_t row = (size_t)(kt * 64 + r) * 1536;
            uint32_t off = (uint32_t)(r * 72 + c8) * 2;
            cp16(base + off, ksec + row + c8);
            cp16(base + 9216 + off, vsec + row + c8);
        }
        asm volatile("cp.async.commit_group;" ::: "memory");
    };

    for (int i = t; i < 225; i += 256)
        btab[i] = btab_g[i * 8 + hh] * LOG2E - BSHIFT;
    for (int i = t; i < 1024; i += 256) {
        int r = i >> 3, c8 = (i & 7) * 8;
        *(uint4*)(sq + r * 72 + c8) =
            *(const uint4*)(qsec + (size_t)(qb * 128 + r) * 1536 + c8);
    }
    issueKV(0);
    issueKV(1);
    issueKV(2);
    __syncthreads();
    float cb = btab[224];   // constant for the fully-clipped region
    uint32_t qf[4][4];
    #pragma unroll
    for (int k = 0; k < 4; k++) {
        uint32_t off = (uint32_t)((wid * 16 + lrow) * 72 + k * 16 + lcb) * 2;
        ldsm_x4(qf[k][0], qf[k][1], qf[k][2], qf[k][3], sb + A_Q + off);
    }

    float oacc[8][4];
    #pragma unroll
    for (int j = 0; j < 8; j++)
        #pragma unroll
        for (int r = 0; r < 4; r++) oacc[j][r] = 0.f;
    float lsum[2] = {0.f, 0.f};
    int trbase = qb * 128 + wid * 16 + (lane >> 2);
    int qy0 = (trbase) >> 5,     qx0 = (trbase) & 31;
    int qy1 = (trbase + 8) >> 5, qx1 = (trbase + 8) & 31;
    int q2 = (lane & 3) * 2;

    #pragma unroll 1
    for (int kt = 0; kt < 16; kt++) {
        int rem = 15 - kt;
        if (rem >= 2)      asm volatile("cp.async.wait_group 2;" ::: "memory");
        else if (rem == 1) asm volatile("cp.async.wait_group 1;" ::: "memory");
        else               asm volatile("cp.async.wait_group 0;" ::: "memory");
        __syncthreads();
        uint32_t kbase = sb + A_KV + (uint32_t)(kt & 3) * KV_STG;
        uint32_t vbase = kbase + 9216;

        bool f0 = (2 * kt + 1) < qy0 + 28;
        bool f1 = (2 * kt + 1) < qy1 + 28;
        float i0v = f0 ? cb : 0.f, i1v = f1 ? cb : 0.f;

        float sacc[8][4];
        #pragma unroll
        for (int j = 0; j < 8; j++) {
            sacc[j][0] = i0v; sacc[j][1] = i0v;
            sacc[j][2] = i1v; sacc[j][3] = i1v;
        }
        #pragma unroll
        for (int k = 0; k < 4; k++) {
            uint32_t bk[4][4];
            #pragma unroll
            for (int g = 0; g < 4; g++) {
                uint32_t off = (uint32_t)((g * 16 + lrow) * 72 + k * 16 + lcb) * 2;
                ldsm_x4(bk[g][0], bk[g][1], bk[g][2], bk[g][3], kbase + off);
            }
            #pragma unroll
            for (int j = 0; j < 8; j++) {
                int g = j >> 1, p = j & 1;
                mma_f16(sacc[j], qf[k], bk[g][p], bk[g][p + 2]);
            }
        }

        uint32_t eh[8][2];
        #pragma unroll
        for (int h = 0; h < 2; h++) {
            bool fast = h ? f1 : f0;
            if (fast) {
                __half2 accs = __floats2half2_rn(0.f, 0.f);
                #pragma unroll
                for (int j = 0; j < 8; j++) {
                    uint32_t v = pack2h(sacc[j][h * 2], sacc[j][h * 2 + 1]);
                    uint32_t e = ex2h2(v);
                    eh[j][h] = e;
                    accs = __hadd2(accs, *(__half2*)&e);
                }
                float2 f = __half22float2(accs);
                lsum[h] += f.x + f.y;
            } else {
                int qy = h ? qy1 : qy0, qx = h ? qx1 : qx0;
                int be = (qy - 2 * kt + 31) * 63 + qx + 31;
                int bo = be - 63;
                float sum = 0.f;
                #pragma unroll
                for (int j = 0; j < 8; j++) {
                    int id0 = ((j < 4) ? be : bo) - ((j & 3) * 8 + q2);
                    int i0 = id0 < 224 ? id0 : 224;
                    int i1 = id0 - 1 < 224 ? id0 - 1 : 224;
                    float e0 = ex2f(sacc[j][h * 2 + 0] + btab[i0]);
                    float e1 = ex2f(sacc[j][h * 2 + 1] + btab[i1]);
                    eh[j][h] = pack2h(e0, e1);
                    sum += e0 + e1;
                }
                lsum[h] += sum;
            }
        }

        uint32_t ap[4][4];
        #pragma unroll
        for (int k = 0; k < 4; k++) {
            ap[k][0] = eh[2 * k][0];
            ap[k][1] = eh[2 * k][1];
            ap[k][2] = eh[2 * k + 1][0];
            ap[k][3] = eh[2 * k + 1][1];
        }

        #pragma unroll
        for (int k = 0; k < 4; k++) {
            uint32_t bv[4][4];
            #pragma unroll
            for (int g = 0; g < 4; g++) {
                uint32_t off = (uint32_t)((k * 16 + lrow) * 72 + g * 16 + lcb) * 2;
                ldsm_x4_t(bv[g][0], bv[g][1], bv[g][2], bv[g][3], vbase + off);
            }
            #pragma unroll
            for (int j = 0; j < 8; j++) {
                int g = j >> 1, p = j & 1;
                mma_f16(oacc[j], ap[k], bv[g][p * 2], bv[g][p * 2 + 1]);
            }
        }
        if (kt + 3 < 16) issueKV(kt + 3);
    }

    #pragma unroll
    for (int h = 0; h < 2; h++) {
        lsum[h] += __shfl_xor_sync(0xffffffffu, lsum[h], 1);
        lsum[h] += __shfl_xor_sync(0xffffffffu, lsum[h], 2);
    }
    if ((lane & 3) == 0) {
        linv[wid * 16 + (lane >> 2)]     = 1.f / lsum[0];
        linv[wid * 16 + (lane >> 2) + 8] = 1.f / lsum[1];
    }
    __syncthreads();
    float* ow = (float*)sm_ + wid * 16 * 66;
    #pragma unroll
    for (int j = 0; j < 8; j++) {
        int c = j * 8 + (lane & 3) * 2;
        int r = lane >> 2;
        ow[r * 66 + c]           = oacc[j][0];
        ow[r * 66 + c + 1]       = oacc[j][1];
        ow[(r + 8) * 66 + c]     = oacc[j][2];
        ow[(r + 8) * 66 + c + 1] = oacc[j][3];
    }
    __syncwarp();
    for (int i = lane; i < 256; i += 32) {
        int r = i >> 4, cg = (i & 15) * 4;
        float inv = linv[wid * 16 + r];
        uint2 u;
        u.x = pack2h(ow[r * 66 + cg] * inv,     ow[r * 66 + cg + 1] * inv);
        u.y = pack2h(ow[r * 66 + cg + 2] * inv, ow[r * 66 + cg + 3] * inv);
        size_t go = ((size_t)bb * 1024 + qb * 128 + wid * 16 + r) * 512 + hh * 64 + cg;
        *(uint2*)(o_g + go) = u;
    }
}

// ---------------------------------------------------------------------------
// Launcher
// ---------------------------------------------------------------------------
extern "C" void kernel_launch(void* const* d_in, const int* in_sizes, int n_in,
                              void* d_out, int out_size)
{
    const float* x      = (const float*)d_in[0];
    const float* qkv_w  = (const float*)d_in[1];
    const float* proj_w = (const float*)d_in[2];
    const float* proj_b = (const float*)d_in[3];
    const float* mlp_w1 = (const float*)d_in[4];
    const float* mlp_b1 = (const float*)d_in[5];
    const float* mlp_w2 = (const float*)d_in[6];
    const float* mlp_b2 = (const float*)d_in[7];
    const float* n1g    = (const float*)d_in[8];
    const float* n1b    = (const float*)d_in[9];
    const float* n2g    = (const float*)d_in[10];
    const float* n2b    = (const float*)d_in[11];
    const float* btab   = (const float*)d_in[12];
    float* out = (float*)d_out;

    float* x1;
    cudaGetSymbolAddress((void**)&x1, d_x1);
    __half *h_, *o_, *hid, *qkv, *wq, *wp, *w1, *w2;
    cudaGetSymbolAddress((void**)&h_,  g_h);
    cudaGetSymbolAddress((void**)&o_,  g_o);
    cudaGetSymbolAddress((void**)&hid, g_hid);
    cudaGetSymbolAddress((void**)&qkv, g_qkv);
    cudaGetSymbolAddress((void**)&wq,  g_wqkv);
    cudaGetSymbolAddress((void**)&wp,  g_wprj);
    cudaGetSymbolAddress((void**)&w1,  g_w1);
    cudaGetSymbolAddress((void**)&w2,  g_w2);

    cudaFuncSetAttribute(attn_tc_kernel,
        cudaFuncAttributeMaxDynamicSharedMemorySize, ATTN_SMEM);
    cudaFuncSetAttribute(mma_gemm<512, EPI_QKV>,
        cudaFuncAttributeMaxDynamicSharedMemorySize, GEMM_SMEM);
    cudaFuncSetAttribute(mma_gemm<512, EPI_PROJ>,
        cudaFuncAttributeMaxDynamicSharedMemorySize, GEMM_SMEM);
    cudaFuncSetAttribute(mma_gemm<512, EPI_GELU>,
        cudaFuncAttributeMaxDynamicSharedMemorySize, GEMM_SMEM);
    cudaFuncSetAttribute(mma_gemm<2048, EPI_OUT>,
        cudaFuncAttributeMaxDynamicSharedMemorySize, GEMM_SMEM);

    cvt4_kernel<<<3072, 256>>>(qkv_w, wq, proj_w, wp, mlp_w1, w1, mlp_w2, w2);

    // LN1 (2 rows per block)
    ln_h_kernel<<<MROWS / 2, 256>>>(x, n1g, n1b, h_);
    // QKV (N=1536) -> [m][1536], q pre-scaled by 0.125*log2e
    mma_gemm<512, EPI_QKV><<<dim3(12, 256), 256, GEMM_SMEM>>>(
        h_, wq, nullptr, nullptr, nullptr, qkv, 1536);
    // attention
    attn_tc_kernel<<<dim3(8, 256), 256, ATTN_SMEM>>>(qkv, btab, o_);
    // proj + residual (N=512)
    mma_gemm<512, EPI_PROJ><<<dim3(4, 256), 256, GEMM_SMEM>>>(
        o_, wp, proj_b, x, x1, nullptr, 512);
    // LN2 (2 rows per block)
    ln_h_kernel<<<MROWS / 2, 256>>>(x1, n2g, n2b, h_);
    // MLP1 + GELU (N=2048)
    mma_gemm<512, EPI_GELU><<<dim3(16, 256), 256, GEMM_SMEM>>>(
        h_, w1, mlp_b1, nullptr, nullptr, hid, 2048);
    // MLP2 + residual -> out (N=512, K=2048)
    mma_gemm<2048, EPI_OUT><<<dim3(4, 256), 256, GEMM_SMEM>>>(
        hid, w2, mlp_b2, x1, out, nullptr, 512);
}

// round 16
// speedup vs baseline: 1.1105x; 1.0135x over previous
#include <cuda_runtime.h>
#include <cuda_fp16.h>
#include <math.h>
#include <stdint.h>

// ---------------------------------------------------------------------------
// B=32, N=1024, DIM=512, HEADS=8, HEAD_DIM=64, MLP_HIDDEN=2048. M = 32768.
// fp16 mma.sync; GEMM 8 warps 64x32, k64, 3-stage cp.async.
// Attention: 8 warps x 16 q-rows, fixed-shift softmax, f16-accumulator S-MMA
// (S result == exp2 input == P fragment), 3-stage KV pipeline, 3 CTAs/SM.
// ---------------------------------------------------------------------------
#define MROWS 32768
#define DIMC  512
#define HIDC  2048

__device__ float d_x1[MROWS * DIMC];
__device__ __half g_h  [MROWS * DIMC];
__device__ __half g_o  [MROWS * DIMC];
__device__ __half g_hid[MROWS * HIDC];
__device__ __half g_qkv[MROWS * 1536];
__device__ __half g_wqkv[1536 * 512];
__device__ __half g_wprj[512 * 512];
__device__ __half g_w1 [2048 * 512];
__device__ __half g_w2 [512 * 2048];

__device__ __forceinline__ uint32_t smem_u32(const void* p) {
    uint32_t a;
    asm("{ .reg .u64 t; cvta.to.shared.u64 t, %1; cvt.u32.u64 %0, t; }"
        : "=r"(a) : "l"(p));
    return a;
}
__device__ __forceinline__ void ldsm_x4(uint32_t& r0, uint32_t& r1,
                                        uint32_t& r2, uint32_t& r3, uint32_t a) {
    asm volatile("ldmatrix.sync.aligned.m8n8.x4.shared.b16 {%0,%1,%2,%3}, [%4];"
                 : "=r"(r0), "=r"(r1), "=r"(r2), "=r"(r3) : "r"(a));
}
__device__ __forceinline__ void ldsm_x4_t(uint32_t& r0, uint32_t& r1,
                                          uint32_t& r2, uint32_t& r3, uint32_t a) {
    asm volatile("ldmatrix.sync.aligned.m8n8.x4.trans.shared.b16 {%0,%1,%2,%3}, [%4];"
                 : "=r"(r0), "=r"(r1), "=r"(r2), "=r"(r3) : "r"(a));
}
__device__ __forceinline__ void mma_f16(float* d, const uint32_t* a,
                                        uint32_t b0, uint32_t b1) {
    asm volatile("mma.sync.aligned.m16n8k16.row.col.f32.f16.f16.f32 "
                 "{%0,%1,%2,%3}, {%4,%5,%6,%7}, {%8,%9}, {%0,%1,%2,%3};"
                 : "+f"(d[0]), "+f"(d[1]), "+f"(d[2]), "+f"(d[3])
                 : "r"(a[0]), "r"(a[1]), "r"(a[2]), "r"(a[3]), "r"(b0), "r"(b1));
}
__device__ __forceinline__ void mma_f16acc(uint32_t* d, const uint32_t* a,
                                           uint32_t b0, uint32_t b1) {
    asm volatile("mma.sync.aligned.m16n8k16.row.col.f16.f16.f16.f16 "
                 "{%0,%1}, {%2,%3,%4,%5}, {%6,%7}, {%0,%1};"
                 : "+r"(d[0]), "+r"(d[1])
                 : "r"(a[0]), "r"(a[1]), "r"(a[2]), "r"(a[3]), "r"(b0), "r"(b1));
}
__device__ __forceinline__ void cp16(uint32_t s, const void* g) {
    asm volatile("cp.async.cg.shared.global [%0], [%1], 16;" :: "r"(s), "l"(g));
}
__device__ __forceinline__ uint32_t pack2h(float x, float y) {
    __half2 h = __floats2half2_rn(x, y);
    return *(uint32_t*)&h;
}
__device__ __forceinline__ float ex2f(float x) {
    float y;
    asm("ex2.approx.f32 %0, %1;" : "=f"(y) : "f"(x));
    return y;
}
__device__ __forceinline__ uint32_t ex2h2(uint32_t v) {
    uint32_t e;
    asm("ex2.approx.f16x2 %0, %1;" : "=r"(e) : "r"(v));
    return e;
}
__device__ __forceinline__ float gelu1(float u) {
    return 0.5f * u * (1.f + erff(u * 0.70710678118654752f));
}

// ---------------------------------------------------------------------------
// LayerNorm -> fp16 : 2 rows per 256-thread block
// ---------------------------------------------------------------------------
__global__ void __launch_bounds__(256) ln_h_kernel(
    const float* __restrict__ x, const float* __restrict__ g,
    const float* __restrict__ b, __half* __restrict__ oh)
{
    int sub = threadIdx.x >> 7;
    int row = blockIdx.x * 2 + sub;
    int t = threadIdx.x & 127;
    float4 vv = reinterpret_cast<const float4*>(x + (size_t)row * DIMC)[t];
    float s  = vv.x + vv.y + vv.z + vv.w;
    float sq = vv.x*vv.x + vv.y*vv.y + vv.z*vv.z + vv.w*vv.w;
    #pragma unroll
    for (int o = 16; o > 0; o >>= 1) {
        s  += __shfl_xor_sync(0xffffffffu, s,  o);
        sq += __shfl_xor_sync(0xffffffffu, sq, o);
    }
    __shared__ float ss[8], sq2[8];
    int w = threadIdx.x >> 5;
    if ((t & 31) == 0) { ss[w] = s; sq2[w] = sq; }
    __syncthreads();
    int wb = sub * 4;
    s  = ss[wb] + ss[wb+1] + ss[wb+2] + ss[wb+3];
    sq = sq2[wb] + sq2[wb+1] + sq2[wb+2] + sq2[wb+3];
    float mu  = s * (1.f / DIMC);
    float var = sq * (1.f / DIMC) - mu * mu;
    float inv = rsqrtf(var + 1e-5f);
    float4 gv = reinterpret_cast<const float4*>(g)[t];
    float4 bv = reinterpret_cast<const float4*>(b)[t];
    uint2 u;
    u.x = pack2h((vv.x - mu) * inv * gv.x + bv.x, (vv.y - mu) * inv * gv.y + bv.y);
    u.y = pack2h((vv.z - mu) * inv * gv.z + bv.z, (vv.w - mu) * inv * gv.w + bv.w);
    *(uint2*)(oh + (size_t)row * DIMC + t * 4) = u;
}

// merged fp32->fp16 weight convert
__global__ void __launch_bounds__(256) cvt4_kernel(
    const float* __restrict__ a0, __half* __restrict__ o0,
    const float* __restrict__ a1, __half* __restrict__ o1,
    const float* __restrict__ a2, __half* __restrict__ o2,
    const float* __restrict__ a3, __half* __restrict__ o3)
{
    int i = blockIdx.x * 256 + threadIdx.x;
    const float* src; __half* dst; int off;
    if (i < 196608)      { src = a0; dst = o0; off = i; }
    else if (i < 262144) { src = a1; dst = o1; off = i - 196608; }
    else if (i < 524288) { src = a2; dst = o2; off = i - 262144; }
    else                 { src = a3; dst = o3; off = i - 524288; }
    float4 v = reinterpret_cast<const float4*>(src)[off];
    uint2 u;
    u.x = pack2h(v.x, v.y);
    u.y = pack2h(v.z, v.w);
    *(uint2*)(dst + (size_t)off * 4) = u;
}

// ---------------------------------------------------------------------------
// Warp-MMA fp16 GEMM: 8 warps 64x32 tiles, CTA 128x128, k-chunk 64,
// 3-stage cp.async pipeline, direct epilogue. (unchanged)
// ---------------------------------------------------------------------------
enum { EPI_QKV = 0, EPI_PROJ = 1, EPI_GELU = 2, EPI_OUT = 3 };

#define LDT 72
#define OFF_A 0
#define OFF_B 18432
#define STG   36864
#define GEMM_SMEM (3 * STG)

#define QSCALE 0.1803368801111244f

template<int KTOT, int EPI>
__global__ void __launch_bounds__(256) mma_gemm(
    const __half* __restrict__ A, const __half* __restrict__ B,
    const float* __restrict__ bias, const float* __restrict__ resid,
    float* __restrict__ out0, __half* __restrict__ oh, int N)
{
    extern __shared__ __align__(128) char dsm[];
    uint32_t sb = smem_u32(dsm);
    int t = threadIdx.x, wid = t >> 5, lane = t & 31;
    int m0 = blockIdx.y << 7, n0 = blockIdx.x << 7;
    int warp_m = wid & 1, warp_n = wid >> 1;

    float acc[4][4][4];
    #pragma unroll
    for (int i = 0; i < 4; i++)
        #pragma unroll
        for (int j = 0; j < 4; j++)
            #pragma unroll
            for (int r = 0; r < 4; r++) acc[i][j][r] = 0.f;

    int lrow = lane & 15, lcb = (lane >> 4) << 3;
    const int NCH = KTOT / 64;

    auto issue = [&](int stg, int k0) {
        #pragma unroll
        for (int i = t; i < 1024; i += 256) {
            int r = i >> 3, q = i & 7;
            size_t ga = (size_t)(m0 + r) * KTOT + k0 + q * 8;
            size_t gb = (size_t)(n0 + r) * KTOT + k0 + q * 8;
            uint32_t off = (uint32_t)stg * STG + (uint32_t)(r * LDT + q * 8) * 2;
            cp16(sb + off + OFF_A, A + ga);
            cp16(sb + off + OFF_B, B + gb);
        }
        asm volatile("cp.async.commit_group;" ::: "memory");
    };

    issue(0, 0);
    issue(1, 64);
    #pragma unroll 1
    for (int ch = 0; ch < NCH; ch++) {
        if (ch + 1 < NCH)
            asm volatile("cp.async.wait_group 1;" ::: "memory");
        else
            asm volatile("cp.async.wait_group 0;" ::: "memory");
        __syncthreads();
        uint32_t stb = sb + (uint32_t)(ch % 3) * STG;
        #pragma unroll
        for (int k16 = 0; k16 < 4; k16++) {
            uint32_t af[4][4], bf[2][4];
            int col = k16 * 16 + lcb;
            #pragma unroll
            for (int am = 0; am < 4; am++) {
                uint32_t off = (uint32_t)((warp_m * 64 + am * 16 + lrow) * LDT + col) * 2;
                ldsm_x4(af[am][0], af[am][1], af[am][2], af[am][3], stb + OFF_A + off);
            }
            #pragma unroll
            for (int an2 = 0; an2 < 2; an2++) {
                uint32_t off = (uint32_t)((warp_n * 32 + an2 * 16 + lrow) * LDT + col) * 2;
                ldsm_x4(bf[an2][0], bf[an2][1], bf[an2][2], bf[an2][3], stb + OFF_B + off);
            }
            #pragma unroll
            for (int am = 0; am < 4; am++)
                #pragma unroll
                for (int an = 0; an < 4; an++) {
                    int a2 = an >> 1, p = an & 1;
                    mma_f16(acc[am][an], af[am], bf[a2][p], bf[a2][p + 2]);
                }
        }
        if (ch + 2 < NCH) issue((ch + 2) % 3, (ch + 2) * 64);
    }

    int rbase = m0 + warp_m * 64 + (lane >> 2);
    int cbase = n0 + warp_n * 32 + (lane & 3) * 2;

    if (EPI == EPI_QKV) {
        float sc = (n0 < 512) ? QSCALE : 1.f;
        #pragma unroll
        for (int am = 0; am < 4; am++) {
            #pragma unroll
            for (int an = 0; an < 4; an++) {
                int n = cbase + an * 8;
                #pragma unroll
                for (int h2 = 0; h2 < 2; h2++) {
                    int m = rbase + am * 16 + h2 * 8;
                    *(uint32_t*)(oh + (size_t)m * 1536 + n) =
                        pack2h(acc[am][an][2 * h2] * sc, acc[am][an][2 * h2 + 1] * sc);
                }
            }
        }
    } else if (EPI == EPI_GELU) {
        float2 bv[4];
        #pragma unroll
        for (int an = 0; an < 4; an++)
            bv[an] = *(const float2*)(bias + cbase + an * 8);
        #pragma unroll
        for (int am = 0; am < 4; am++) {
            #pragma unroll
            for (int an = 0; an < 4; an++) {
                int n = cbase + an * 8;
                #pragma unroll
                for (int h2 = 0; h2 < 2; h2++) {
                    int m = rbase + am * 16 + h2 * 8;
                    float g0 = gelu1(acc[am][an][2 * h2]     + bv[an].x);
                    float g1 = gelu1(acc[am][an][2 * h2 + 1] + bv[an].y);
                    *(uint32_t*)(oh + (size_t)m * HIDC + n) = pack2h(g0, g1);
                }
            }
        }
    } else {
        float2 bv[4];
        #pragma unroll
        for (int an = 0; an < 4; an++)
            bv[an] = *(const float2*)(bias + cbase + an * 8);
        #pragma unroll
        for (int am = 0; am < 4; am++) {
            #pragma unroll
            for (int an = 0; an < 4; an++) {
                int n = cbase + an * 8;
                #pragma unroll
                for (int h2 = 0; h2 < 2; h2++) {
                    int m = rbase + am * 16 + h2 * 8;
                    float2 rv = *(const float2*)(resid + (size_t)m * N + n);
                    float2 o2;
                    o2.x = rv.x + acc[am][an][2 * h2]     + bv[an].x;
                    o2.y = rv.y + acc[am][an][2 * h2 + 1] + bv[an].y;
                    *(float2*)(out0 + (size_t)m * N + n) = o2;
                }
            }
        }
    }
}

// ---------------------------------------------------------------------------
// fp16 flash attention: f16-acc S-MMA, fixed-shift softmax, 3-stage KV
// pipeline, 3 CTAs/SM target.
// ---------------------------------------------------------------------------
#define A_Q  0u
#define A_KV 18432u
#define KV_STG 18432u
#define A_BT 73728u
#define A_LI 74752u
#define ATTN_SMEM 75264
#define LOG2E 1.4426950408889634f
#define BSHIFT (4.0f * LOG2E)

__global__ void __launch_bounds__(256, 3) attn_tc_kernel(
    const __half* __restrict__ qkv_g, const float* __restrict__ btab_g,
    __half* __restrict__ o_g)
{
    extern __shared__ char sm_[];
    __half* sq = (__half*)(sm_ + A_Q);
    float* btab = (float*)(sm_ + A_BT);
    float* linv = (float*)(sm_ + A_LI);
    uint32_t sb = smem_u32(sm_);

    int qb = blockIdx.x, bh = blockIdx.y;
    int hh = bh & 7, bb = bh >> 3;
    int t = threadIdx.x, wid = t >> 5, lane = t & 31;
    int lrow = lane & 15, lcb = (lane >> 4) << 3;

    const __half* qsec = qkv_g + (size_t)bb * 1024 * 1536 + hh * 64;
    const __half* ksec = qsec + 512;
    const __half* vsec = qsec + 1024;

    auto issueKV = [&](int kt) {
        uint32_t base = sb + A_KV + (uint32_t)(kt % 3) * KV_STG;
        #pragma unroll
        for (int i = t; i < 512; i += 256) {
            int r = i >> 3, c8 = (i & 7) * 8;
            size_t row = (size_t)(kt * 64 + r) * 1536;
            uint32_t off = (uint32_t)(r * 72 + c8) * 2;
            cp16(base + off, ksec + row + c8);
            cp16(base + 9216 + off, vsec + row + c8);
        }
        asm volatile("cp.async.commit_group;" ::: "memory");
    };

    for (int i = t; i < 225; i += 256)
        btab[i] = btab_g[i * 8 + hh] * LOG2E - BSHIFT;
    for (int i = t; i < 1024; i += 256) {
        int r = i >> 3, c8 = (i & 7) * 8;
        *(uint4*)(sq + r * 72 + c8) =
            *(const uint4*)(qsec + (size_t)(qb * 128 + r) * 1536 + c8);
    }
    issueKV(0);
    issueKV(1);
    __syncthreads();
    float cb = btab[224];
    uint32_t cbh2;
    { __half2 c2 = __float2half2_rn(cb); cbh2 = *(uint32_t*)&c2; }
    uint32_t qf[4][4];
    #pragma unroll
    for (int k = 0; k < 4; k++) {
        uint32_t off = (uint32_t)((wid * 16 + lrow) * 72 + k * 16 + lcb) * 2;
        ldsm_x4(qf[k][0], qf[k][1], qf[k][2], qf[k][3], sb + A_Q + off);
    }

    float oacc[8][4];
    #pragma unroll
    for (int j = 0; j < 8; j++)
        #pragma unroll
        for (int r = 0; r < 4; r++) oacc[j][r] = 0.f;
    float lsum[2] = {0.f, 0.f};
    int trbase = qb * 128 + wid * 16 + (lane >> 2);
    int qy0 = (trbase) >> 5,     qx0 = (trbase) & 31;
    int qy1 = (trbase + 8) >> 5, qx1 = (trbase + 8) & 31;
    int q2 = (lane & 3) * 2;

    #pragma unroll 1
    for (int kt = 0; kt < 16; kt++) {
        if (kt < 15)
            asm volatile("cp.async.wait_group 1;" ::: "memory");
        else
            asm volatile("cp.async.wait_group 0;" ::: "memory");
        __syncthreads();
        uint32_t kbase = sb + A_KV + (uint32_t)(kt % 3) * KV_STG;
        uint32_t vbase = kbase + 9216;

        bool f0 = (2 * kt + 1) < qy0 + 28;
        bool f1 = (2 * kt + 1) < qy1 + 28;
        uint32_t i0h = f0 ? cbh2 : 0u, i1h = f1 ? cbh2 : 0u;

        // S = Q K^T with f16 accumulator, bias pre-seeded (fast path)
        uint32_t sacc[8][2];
        #pragma unroll
        for (int j = 0; j < 8; j++) { sacc[j][0] = i0h; sacc[j][1] = i1h; }
        #pragma unroll
        for (int k = 0; k < 4; k++) {
            uint32_t bk[4][4];
            #pragma unroll
            for (int g = 0; g < 4; g++) {
                uint32_t off = (uint32_t)((g * 16 + lrow) * 72 + k * 16 + lcb) * 2;
                ldsm_x4(bk[g][0], bk[g][1], bk[g][2], bk[g][3], kbase + off);
            }
            #pragma unroll
            for (int j = 0; j < 8; j++) {
                int g = j >> 1, p = j & 1;
                mma_f16acc(sacc[j], qf[k], bk[g][p], bk[g][p + 2]);
            }
        }

        // exponent in-place: sacc becomes P fragments
        #pragma unroll
        for (int h = 0; h < 2; h++) {
            bool fast = h ? f1 : f0;
            if (fast) {
                __half2 accs = __floats2half2_rn(0.f, 0.f);
                #pragma unroll
                for (int j = 0; j < 8; j++) {
                    uint32_t e = ex2h2(sacc[j][h]);
                    sacc[j][h] = e;
                    accs = __hadd2(accs, *(__half2*)&e);
                }
                float2 f = __half22float2(accs);
                lsum[h] += f.x + f.y;
            } else {
                int qy = h ? qy1 : qy0, qx = h ? qx1 : qx0;
                int be = (qy - 2 * kt + 31) * 63 + qx + 31;
                int bo = be - 63;
                float sum = 0.f;
                #pragma unroll
                for (int j = 0; j < 8; j++) {
                    __half2 sv = *(__half2*)&sacc[j][h];
                    int id0 = ((j < 4) ? be : bo) - ((j & 3) * 8 + q2);
                    int i0 = id0 < 224 ? id0 : 224;
                    int i1 = id0 - 1 < 224 ? id0 - 1 : 224;
                    float e0 = ex2f(__half2float(sv.x) + btab[i0]);
                    float e1 = ex2f(__half2float(sv.y) + btab[i1]);
                    sacc[j][h] = pack2h(e0, e1);
                    sum += e0 + e1;
                }
                lsum[h] += sum;
            }
        }

        // O += P V, V [seq][d] via ldmatrix.trans; A fragments from sacc
        #pragma unroll
        for (int k = 0; k < 4; k++) {
            uint32_t bv[4][4];
            #pragma unroll
            for (int g = 0; g < 4; g++) {
                uint32_t off = (uint32_t)((k * 16 + lrow) * 72 + g * 16 + lcb) * 2;
                ldsm_x4_t(bv[g][0], bv[g][1], bv[g][2], bv[g][3], vbase + off);
            }
            uint32_t ap[4] = {sacc[2*k][0], sacc[2*k][1],
                              sacc[2*k+1][0], sacc[2*k+1][1]};
            #pragma unroll
            for (int j = 0; j < 8; j++) {
                int g = j >> 1, p = j & 1;
                mma_f16(oacc[j], ap, bv[g][p * 2], bv[g][p * 2 + 1]);
            }
        }
        if (kt + 2 < 16) issueKV(kt + 2);
    }

    #pragma unroll
    for (int h = 0; h < 2; h++) {
        lsum[h] += __shfl_xor_sync(0xffffffffu, lsum[h], 1);
        lsum[h] += __shfl_xor_sync(0xffffffffu, lsum[h], 2);
    }
    if ((lane & 3) == 0) {
        linv[wid * 16 + (lane >> 2)]     = 1.f / lsum[0];
        linv[wid * 16 + (lane >> 2) + 8] = 1.f / lsum[1];
    }
    __syncthreads();
    float* ow = (float*)sm_ + wid * 16 * 66;
    #pragma unroll
    for (int j = 0; j < 8; j++) {
        int c = j * 8 + (lane & 3) * 2;
        int r = lane >> 2;
        ow[r * 66 + c]           = oacc[j][0];
        ow[r * 66 + c + 1]       = oacc[j][1];
        ow[(r + 8) * 66 + c]     = oacc[j][2];
        ow[(r + 8) * 66 + c + 1] = oacc[j][3];
    }
    __syncwarp();
    for (int i = lane; i < 256; i += 32) {
        int r = i >> 4, cg = (i & 15) * 4;
        float inv = linv[wid * 16 + r];
        uint2 u;
        u.x = pack2h(ow[r * 66 + cg] * inv,     ow[r * 66 + cg + 1] * inv);
        u.y = pack2h(ow[r * 66 + cg + 2] * inv, ow[r * 66 + cg + 3] * inv);
        size_t go = ((size_t)bb * 1024 + qb * 128 + wid * 16 + r) * 512 + hh * 64 + cg;
        *(uint2*)(o_g + go) = u;
    }
}

// ---------------------------------------------------------------------------
// Launcher
// ---------------------------------------------------------------------------
extern "C" void kernel_launch(void* const* d_in, const int* in_sizes, int n_in,
                              void* d_out, int out_size)
{
    const float* x      = (const float*)d_in[0];
    const float* qkv_w  = (const float*)d_in[1];
    const float* proj_w = (const float*)d_in[2];
    const float* proj_b = (const float*)d_in[3];
    const float* mlp_w1 = (const float*)d_in[4];
    const float* mlp_b1 = (const float*)d_in[5];
    const float* mlp_w2 = (const float*)d_in[6];
    const float* mlp_b2 = (const float*)d_in[7];
    const float* n1g    = (const float*)d_in[8];
    const float* n1b    = (const float*)d_in[9];
    const float* n2g    = (const float*)d_in[10];
    const float* n2b    = (const float*)d_in[11];
    const float* btab   = (const float*)d_in[12];
    float* out = (float*)d_out;

    float* x1;
    cudaGetSymbolAddress((void**)&x1, d_x1);
    __half *h_, *o_, *hid, *qkv, *wq, *wp, *w1, *w2;
    cudaGetSymbolAddress((void**)&h_,  g_h);
    cudaGetSymbolAddress((void**)&o_,  g_o);
    cudaGetSymbolAddress((void**)&hid, g_hid);
    cudaGetSymbolAddress((void**)&qkv, g_qkv);
    cudaGetSymbolAddress((void**)&wq,  g_wqkv);
    cudaGetSymbolAddress((void**)&wp,  g_wprj);
    cudaGetSymbolAddress((void**)&w1,  g_w1);
    cudaGetSymbolAddress((void**)&w2,  g_w2);

    cudaFuncSetAttribute(attn_tc_kernel,
        cudaFuncAttributeMaxDynamicSharedMemorySize, ATTN_SMEM);
    cudaFuncSetAttribute(mma_gemm<512, EPI_QKV>,
        cudaFuncAttributeMaxDynamicSharedMemorySize, GEMM_SMEM);
    cudaFuncSetAttribute(mma_gemm<512, EPI_PROJ>,
        cudaFuncAttributeMaxDynamicSharedMemorySize, GEMM_SMEM);
    cudaFuncSetAttribute(mma_gemm<512, EPI_GELU>,
        cudaFuncAttributeMaxDynamicSharedMemorySize, GEMM_SMEM);
    cudaFuncSetAttribute(mma_gemm<2048, EPI_OUT>,
        cudaFuncAttributeMaxDynamicSharedMemorySize, GEMM_SMEM);

    cvt4_kernel<<<3072, 256>>>(qkv_w, wq, proj_w, wp, mlp_w1, w1, mlp_w2, w2);

    // LN1 (2 rows per block)
    ln_h_kernel<<<MROWS / 2, 256>>>(x, n1g, n1b, h_);
    // QKV (N=1536) -> [m][1536], q pre-scaled by 0.125*log2e
    mma_gemm<512, EPI_QKV><<<dim3(12, 256), 256, GEMM_SMEM>>>(
        h_, wq, nullptr, nullptr, nullptr, qkv, 1536);
    // attention
    attn_tc_kernel<<<dim3(8, 256), 256, ATTN_SMEM>>>(qkv, btab, o_);
    // proj + residual (N=512)
    mma_gemm<512, EPI_PROJ><<<dim3(4, 256), 256, GEMM_SMEM>>>(
        o_, wp, proj_b, x, x1, nullptr, 512);
    // LN2 (2 rows per block)
    ln_h_kernel<<<MROWS / 2, 256>>>(x1, n2g, n2b, h_);
    // MLP1 + GELU (N=2048)
    mma_gemm<512, EPI_GELU><<<dim3(16, 256), 256, GEMM_SMEM>>>(
        h_, w1, mlp_b1, nullptr, nullptr, hid, 2048);
    // MLP2 + residual -> out (N=512, K=2048)
    mma_gemm<2048, EPI_OUT><<<dim3(4, 256), 256, GEMM_SMEM>>>(
        hid, w2, mlp_b2, x1, out, nullptr, 512);
}

// round 17
// speedup vs baseline: 1.1440x; 1.0302x over previous
#include <cuda_runtime.h>
#include <cuda_fp16.h>
#include <math.h>
#include <stdint.h>

// ---------------------------------------------------------------------------
// B=32, N=1024, DIM=512, HEADS=8, HEAD_DIM=64, MLP_HIDDEN=2048. M = 32768.
// fp16 mma.sync; GEMM 8 warps 64x32, k64, 3-stage cp.async.
// Attention: 8 warps x 16 q-rows, fixed-shift softmax, f16-acc S-MMA,
// 3-stage KV pipeline, 3 CTAs/SM. R16: hoisted cp.async address math.
// ---------------------------------------------------------------------------
#define MROWS 32768
#define DIMC  512
#define HIDC  2048

__device__ float d_x1[MROWS * DIMC];
__device__ __half g_h  [MROWS * DIMC];
__device__ __half g_o  [MROWS * DIMC];
__device__ __half g_hid[MROWS * HIDC];
__device__ __half g_qkv[MROWS * 1536];
__device__ __half g_wqkv[1536 * 512];
__device__ __half g_wprj[512 * 512];
__device__ __half g_w1 [2048 * 512];
__device__ __half g_w2 [512 * 2048];

__device__ __forceinline__ uint32_t smem_u32(const void* p) {
    uint32_t a;
    asm("{ .reg .u64 t; cvta.to.shared.u64 t, %1; cvt.u32.u64 %0, t; }"
        : "=r"(a) : "l"(p));
    return a;
}
__device__ __forceinline__ void ldsm_x4(uint32_t& r0, uint32_t& r1,
                                        uint32_t& r2, uint32_t& r3, uint32_t a) {
    asm volatile("ldmatrix.sync.aligned.m8n8.x4.shared.b16 {%0,%1,%2,%3}, [%4];"
                 : "=r"(r0), "=r"(r1), "=r"(r2), "=r"(r3) : "r"(a));
}
__device__ __forceinline__ void ldsm_x4_t(uint32_t& r0, uint32_t& r1,
                                          uint32_t& r2, uint32_t& r3, uint32_t a) {
    asm volatile("ldmatrix.sync.aligned.m8n8.x4.trans.shared.b16 {%0,%1,%2,%3}, [%4];"
                 : "=r"(r0), "=r"(r1), "=r"(r2), "=r"(r3) : "r"(a));
}
__device__ __forceinline__ void mma_f16(float* d, const uint32_t* a,
                                        uint32_t b0, uint32_t b1) {
    asm volatile("mma.sync.aligned.m16n8k16.row.col.f32.f16.f16.f32 "
                 "{%0,%1,%2,%3}, {%4,%5,%6,%7}, {%8,%9}, {%0,%1,%2,%3};"
                 : "+f"(d[0]), "+f"(d[1]), "+f"(d[2]), "+f"(d[3])
                 : "r"(a[0]), "r"(a[1]), "r"(a[2]), "r"(a[3]), "r"(b0), "r"(b1));
}
__device__ __forceinline__ void mma_f16acc(uint32_t* d, const uint32_t* a,
                                           uint32_t b0, uint32_t b1) {
    asm volatile("mma.sync.aligned.m16n8k16.row.col.f16.f16.f16.f16 "
                 "{%0,%1}, {%2,%3,%4,%5}, {%6,%7}, {%0,%1};"
                 : "+r"(d[0]), "+r"(d[1])
                 : "r"(a[0]), "r"(a[1]), "r"(a[2]), "r"(a[3]), "r"(b0), "r"(b1));
}
__device__ __forceinline__ void cp16(uint32_t s, const void* g) {
    asm volatile("cp.async.cg.shared.global [%0], [%1], 16;" :: "r"(s), "l"(g));
}
__device__ __forceinline__ uint32_t pack2h(float x, float y) {
    __half2 h = __floats2half2_rn(x, y);
    return *(uint32_t*)&h;
}
__device__ __forceinline__ float ex2f(float x) {
    float y;
    asm("ex2.approx.f32 %0, %1;" : "=f"(y) : "f"(x));
    return y;
}
__device__ __forceinline__ uint32_t ex2h2(uint32_t v) {
    uint32_t e;
    asm("ex2.approx.f16x2 %0, %1;" : "=r"(e) : "r"(v));
    return e;
}
__device__ __forceinline__ float gelu1(float u) {
    return 0.5f * u * (1.f + erff(u * 0.70710678118654752f));
}

// ---------------------------------------------------------------------------
// LayerNorm -> fp16 : 2 rows per 256-thread block
// ---------------------------------------------------------------------------
__global__ void __launch_bounds__(256) ln_h_kernel(
    const float* __restrict__ x, const float* __restrict__ g,
    const float* __restrict__ b, __half* __restrict__ oh)
{
    int sub = threadIdx.x >> 7;
    int row = blockIdx.x * 2 + sub;
    int t = threadIdx.x & 127;
    float4 vv = reinterpret_cast<const float4*>(x + (size_t)row * DIMC)[t];
    float s  = vv.x + vv.y + vv.z + vv.w;
    float sq = vv.x*vv.x + vv.y*vv.y + vv.z*vv.z + vv.w*vv.w;
    #pragma unroll
    for (int o = 16; o > 0; o >>= 1) {
        s  += __shfl_xor_sync(0xffffffffu, s,  o);
        sq += __shfl_xor_sync(0xffffffffu, sq, o);
    }
    __shared__ float ss[8], sq2[8];
    int w = threadIdx.x >> 5;
    if ((t & 31) == 0) { ss[w] = s; sq2[w] = sq; }
    __syncthreads();
    int wb = sub * 4;
    s  = ss[wb] + ss[wb+1] + ss[wb+2] + ss[wb+3];
    sq = sq2[wb] + sq2[wb+1] + sq2[wb+2] + sq2[wb+3];
    float mu  = s * (1.f / DIMC);
    float var = sq * (1.f / DIMC) - mu * mu;
    float inv = rsqrtf(var + 1e-5f);
    float4 gv = reinterpret_cast<const float4*>(g)[t];
    float4 bv = reinterpret_cast<const float4*>(b)[t];
    uint2 u;
    u.x = pack2h((vv.x - mu) * inv * gv.x + bv.x, (vv.y - mu) * inv * gv.y + bv.y);
    u.y = pack2h((vv.z - mu) * inv * gv.z + bv.z, (vv.w - mu) * inv * gv.w + bv.w);
    *(uint2*)(oh + (size_t)row * DIMC + t * 4) = u;
}

// merged fp32->fp16 weight convert
__global__ void __launch_bounds__(256) cvt4_kernel(
    const float* __restrict__ a0, __half* __restrict__ o0,
    const float* __restrict__ a1, __half* __restrict__ o1,
    const float* __restrict__ a2, __half* __restrict__ o2,
    const float* __restrict__ a3, __half* __restrict__ o3)
{
    int i = blockIdx.x * 256 + threadIdx.x;
    const float* src; __half* dst; int off;
    if (i < 196608)      { src = a0; dst = o0; off = i; }
    else if (i < 262144) { src = a1; dst = o1; off = i - 196608; }
    else if (i < 524288) { src = a2; dst = o2; off = i - 262144; }
    else                 { src = a3; dst = o3; off = i - 524288; }
    float4 v = reinterpret_cast<const float4*>(src)[off];
    uint2 u;
    u.x = pack2h(v.x, v.y);
    u.y = pack2h(v.z, v.w);
    *(uint2*)(dst + (size_t)off * 4) = u;
}

// ---------------------------------------------------------------------------
// Warp-MMA fp16 GEMM: 8 warps 64x32 tiles, CTA 128x128, k-chunk 64,
// 3-stage cp.async pipeline, hoisted issue addressing, direct epilogue.
// ---------------------------------------------------------------------------
enum { EPI_QKV = 0, EPI_PROJ = 1, EPI_GELU = 2, EPI_OUT = 3 };

#define LDT 72
#define OFF_A 0
#define OFF_B 18432
#define STG   36864
#define GEMM_SMEM (3 * STG)

#define QSCALE 0.1803368801111244f

template<int KTOT, int EPI>
__global__ void __launch_bounds__(256) mma_gemm(
    const __half* __restrict__ A, const __half* __restrict__ B,
    const float* __restrict__ bias, const float* __restrict__ resid,
    float* __restrict__ out0, __half* __restrict__ oh, int N)
{
    extern __shared__ __align__(128) char dsm[];
    uint32_t sb = smem_u32(dsm);
    int t = threadIdx.x, wid = t >> 5, lane = t & 31;
    int m0 = blockIdx.y << 7, n0 = blockIdx.x << 7;
    int warp_m = wid & 1, warp_n = wid >> 1;

    float acc[4][4][4];
    #pragma unroll
    for (int i = 0; i < 4; i++)
        #pragma unroll
        for (int j = 0; j < 4; j++)
            #pragma unroll
            for (int r = 0; r < 4; r++) acc[i][j][r] = 0.f;

    int lrow = lane & 15, lcb = (lane >> 4) << 3;
    const int NCH = KTOT / 64;

    // hoisted per-thread copy addressing: 4 rows (ir + 32s), fixed col group
    int ir = t >> 3, iq = t & 7;
    const char* Abase = (const char*)A + ((size_t)m0 + ir) * (KTOT * 2) + iq * 16;
    const char* Bbase = (const char*)B + ((size_t)n0 + ir) * (KTOT * 2) + iq * 16;
    uint32_t soff[4];
    #pragma unroll
    for (int s = 0; s < 4; s++)
        soff[s] = (uint32_t)(((ir + 32 * s) * LDT + iq * 8) * 2);
    const size_t rstep = (size_t)32 * KTOT * 2;

    auto issue = [&](int stg, int k0) {
        uint32_t base = sb + (uint32_t)stg * STG;
        const char* Ap = Abase + k0 * 2;
        const char* Bp = Bbase + k0 * 2;
        #pragma unroll
        for (int s = 0; s < 4; s++) {
            cp16(base + OFF_A + soff[s], Ap + rstep * s);
            cp16(base + OFF_B + soff[s], Bp + rstep * s);
        }
        asm volatile("cp.async.commit_group;" ::: "memory");
    };

    issue(0, 0);
    issue(1, 64);
    #pragma unroll 1
    for (int ch = 0; ch < NCH; ch++) {
        if (ch + 1 < NCH)
            asm volatile("cp.async.wait_group 1;" ::: "memory");
        else
            asm volatile("cp.async.wait_group 0;" ::: "memory");
        __syncthreads();
        uint32_t stb = sb + (uint32_t)(ch % 3) * STG;
        #pragma unroll
        for (int k16 = 0; k16 < 4; k16++) {
            uint32_t af[4][4], bf[2][4];
            int col = k16 * 16 + lcb;
            #pragma unroll
            for (int am = 0; am < 4; am++) {
                uint32_t off = (uint32_t)((warp_m * 64 + am * 16 + lrow) * LDT + col) * 2;
                ldsm_x4(af[am][0], af[am][1], af[am][2], af[am][3], stb + OFF_A + off);
            }
            #pragma unroll
            for (int an2 = 0; an2 < 2; an2++) {
                uint32_t off = (uint32_t)((warp_n * 32 + an2 * 16 + lrow) * LDT + col) * 2;
                ldsm_x4(bf[an2][0], bf[an2][1], bf[an2][2], bf[an2][3], stb + OFF_B + off);
            }
            #pragma unroll
            for (int am = 0; am < 4; am++)
                #pragma unroll
                for (int an = 0; an < 4; an++) {
                    int a2 = an >> 1, p = an & 1;
                    mma_f16(acc[am][an], af[am], bf[a2][p], bf[a2][p + 2]);
                }
        }
        if (ch + 2 < NCH) issue((ch + 2) % 3, (ch + 2) * 64);
    }

    int rbase = m0 + warp_m * 64 + (lane >> 2);
    int cbase = n0 + warp_n * 32 + (lane & 3) * 2;

    if (EPI == EPI_QKV) {
        float sc = (n0 < 512) ? QSCALE : 1.f;
        #pragma unroll
        for (int am = 0; am < 4; am++) {
            #pragma unroll
            for (int an = 0; an < 4; an++) {
                int n = cbase + an * 8;
                #pragma unroll
                for (int h2 = 0; h2 < 2; h2++) {
                    int m = rbase + am * 16 + h2 * 8;
                    *(uint32_t*)(oh + (size_t)m * 1536 + n) =
                        pack2h(acc[am][an][2 * h2] * sc, acc[am][an][2 * h2 + 1] * sc);
                }
            }
        }
    } else if (EPI == EPI_GELU) {
        float2 bv[4];
        #pragma unroll
        for (int an = 0; an < 4; an++)
            bv[an] = *(const float2*)(bias + cbase + an * 8);
        #pragma unroll
        for (int am = 0; am < 4; am++) {
            #pragma unroll
            for (int an = 0; an < 4; an++) {
                int n = cbase + an * 8;
                #pragma unroll
                for (int h2 = 0; h2 < 2; h2++) {
                    int m = rbase + am * 16 + h2 * 8;
                    float g0 = gelu1(acc[am][an][2 * h2]     + bv[an].x);
                    float g1 = gelu1(acc[am][an][2 * h2 + 1] + bv[an].y);
                    *(uint32_t*)(oh + (size_t)m * HIDC + n) = pack2h(g0, g1);
                }
            }
        }
    } else {
        float2 bv[4];
        #pragma unroll
        for (int an = 0; an < 4; an++)
            bv[an] = *(const float2*)(bias + cbase + an * 8);
        #pragma unroll
        for (int am = 0; am < 4; am++) {
            #pragma unroll
            for (int an = 0; an < 4; an++) {
                int n = cbase + an * 8;
                #pragma unroll
                for (int h2 = 0; h2 < 2; h2++) {
                    int m = rbase + am * 16 + h2 * 8;
                    float2 rv = *(const float2*)(resid + (size_t)m * N + n);
                    float2 o2;
                    o2.x = rv.x + acc[am][an][2 * h2]     + bv[an].x;
                    o2.y = rv.y + acc[am][an][2 * h2 + 1] + bv[an].y;
                    *(float2*)(out0 + (size_t)m * N + n) = o2;
                }
            }
        }
    }
}

// ---------------------------------------------------------------------------
// fp16 flash attention: f16-acc S-MMA, fixed-shift softmax, 3-stage KV
// pipeline, hoisted issueKV addressing, 3 CTAs/SM.
// ---------------------------------------------------------------------------
#define A_Q  0u
#define A_KV 18432u
#define KV_STG 18432u
#define A_BT 73728u
#define A_LI 74752u
#define ATTN_SMEM 75264
#define LOG2E 1.4426950408889634f
#define BSHIFT (4.0f * LOG2E)

__global__ void __launch_bounds__(256, 3) attn_tc_kernel(
    const __half* __restrict__ qkv_g, const float* __restrict__ btab_g,
    __half* __restrict__ o_g)
{
    extern __shared__ char sm_[];
    __half* sq = (__half*)(sm_ + A_Q);
    float* btab = (float*)(sm_ + A_BT);
    float* linv = (float*)(sm_ + A_LI);
    uint32_t sb = smem_u32(sm_);

    int qb = blockIdx.x, bh = blockIdx.y;
    int hh = bh & 7, bb = bh >> 3;
    int t = threadIdx.x, wid = t >> 5, lane = t & 31;
    int lrow = lane & 15, lcb = (lane >> 4) << 3;

    const __half* qsec = qkv_g + (size_t)bb * 1024 * 1536 + hh * 64;
    const __half* ksec = qsec + 512;
    const __half* vsec = qsec + 1024;

    // hoisted per-thread copy addressing: rows ir, ir+32; fixed col group
    int ir = t >> 3, iq8 = (t & 7) * 8;
    const char* Kbase = (const char*)ksec + (size_t)ir * 3072 + iq8 * 2;
    const char* Vbase = (const char*)vsec + (size_t)ir * 3072 + iq8 * 2;
    uint32_t so0 = (uint32_t)((ir * 72 + iq8) * 2);
    uint32_t so1 = (uint32_t)(((ir + 32) * 72 + iq8) * 2);
    const size_t rstep32 = (size_t)32 * 3072;

    auto issueKV = [&](int kt) {
        uint32_t base = sb + A_KV + (uint32_t)(kt % 3) * KV_STG;
        size_t toff = (size_t)kt * (64 * 3072);
        const char* kp = Kbase + toff;
        const char* vp = Vbase + toff;
        cp16(base + so0, kp);
        cp16(base + so1, kp + rstep32);
        cp16(base + 9216 + so0, vp);
        cp16(base + 9216 + so1, vp + rstep32);
        asm volatile("cp.async.commit_group;" ::: "memory");
    };

    for (int i = t; i < 225; i += 256)
        btab[i] = btab_g[i * 8 + hh] * LOG2E - BSHIFT;
    for (int i = t; i < 1024; i += 256) {
        int r = i >> 3, c8 = (i & 7) * 8;
        *(uint4*)(sq + r * 72 + c8) =
            *(const uint4*)(qsec + (size_t)(qb * 128 + r) * 1536 + c8);
    }
    issueKV(0);
    issueKV(1);
    __syncthreads();
    float cb = btab[224];
    uint32_t cbh2;
    { __half2 c2 = __float2half2_rn(cb); cbh2 = *(uint32_t*)&c2; }
    uint32_t qf[4][4];
    #pragma unroll
    for (int k = 0; k < 4; k++) {
        uint32_t off = (uint32_t)((wid * 16 + lrow) * 72 + k * 16 + lcb) * 2;
        ldsm_x4(qf[k][0], qf[k][1], qf[k][2], qf[k][3], sb + A_Q + off);
    }

    float oacc[8][4];
    #pragma unroll
    for (int j = 0; j < 8; j++)
        #pragma unroll
        for (int r = 0; r < 4; r++) oacc[j][r] = 0.f;
    float lsum[2] = {0.f, 0.f};
    int trbase = qb * 128 + wid * 16 + (lane >> 2);
    int qy0 = (trbase) >> 5,     qx0 = (trbase) & 31;
    int qy1 = (trbase + 8) >> 5, qx1 = (trbase + 8) & 31;
    int q2 = (lane & 3) * 2;

    #pragma unroll 1
    for (int kt = 0; kt < 16; kt++) {
        if (kt < 15)
            asm volatile("cp.async.wait_group 1;" ::: "memory");
        else
            asm volatile("cp.async.wait_group 0;" ::: "memory");
        __syncthreads();
        uint32_t kbase = sb + A_KV + (uint32_t)(kt % 3) * KV_STG;
        uint32_t vbase = kbase + 9216;

        bool f0 = (2 * kt + 1) < qy0 + 28;
        bool f1 = (2 * kt + 1) < qy1 + 28;
        uint32_t i0h = f0 ? cbh2 : 0u, i1h = f1 ? cbh2 : 0u;

        uint32_t sacc[8][2];
        #pragma unroll
        for (int j = 0; j < 8; j++) { sacc[j][0] = i0h; sacc[j][1] = i1h; }
        #pragma unroll
        for (int k = 0; k < 4; k++) {
            uint32_t bk[4][4];
            #pragma unroll
            for (int g = 0; g < 4; g++) {
                uint32_t off = (uint32_t)((g * 16 + lrow) * 72 + k * 16 + lcb) * 2;
                ldsm_x4(bk[g][0], bk[g][1], bk[g][2], bk[g][3], kbase + off);
            }
            #pragma unroll
            for (int j = 0; j < 8; j++) {
                int g = j >> 1, p = j & 1;
                mma_f16acc(sacc[j], qf[k], bk[g][p], bk[g][p + 2]);
            }
        }

        #pragma unroll
        for (int h = 0; h < 2; h++) {
            bool fast = h ? f1 : f0;
            if (fast) {
                __half2 accs = __floats2half2_rn(0.f, 0.f);
                #pragma unroll
                for (int j = 0; j < 8; j++) {
                    uint32_t e = ex2h2(sacc[j][h]);
                    sacc[j][h] = e;
                    accs = __hadd2(accs, *(__half2*)&e);
                }
                float2 f = __half22float2(accs);
                lsum[h] += f.x + f.y;
            } else {
                int qy = h ? qy1 : qy0, qx = h ? qx1 : qx0;
                int be = (qy - 2 * kt + 31) * 63 + qx + 31;
                int bo = be - 63;
                float sum = 0.f;
                #pragma unroll
                for (int j = 0; j < 8; j++) {
                    __half2 sv = *(__half2*)&sacc[j][h];
                    int id0 = ((j < 4) ? be : bo) - ((j & 3) * 8 + q2);
                    int i0 = id0 < 224 ? id0 : 224;
                    int i1 = id0 - 1 < 224 ? id0 - 1 : 224;
                    float e0 = ex2f(__half2float(sv.x) + btab[i0]);
                    float e1 = ex2f(__half2float(sv.y) + btab[i1]);
                    sacc[j][h] = pack2h(e0, e1);
                    sum += e0 + e1;
                }
                lsum[h] += sum;
            }
        }

        #pragma unroll
        for (int k = 0; k < 4; k++) {
            uint32_t bv[4][4];
            #pragma unroll
            for (int g = 0; g < 4; g++) {
                uint32_t off = (uint32_t)((k * 16 + lrow) * 72 + g * 16 + lcb) * 2;
                ldsm_x4_t(bv[g][0], bv[g][1], bv[g][2], bv[g][3], vbase + off);
            }
            uint32_t ap[4] = {sacc[2*k][0], sacc[2*k][1],
                              sacc[2*k+1][0], sacc[2*k+1][1]};
            #pragma unroll
            for (int j = 0; j < 8; j++) {
                int g = j >> 1, p = j & 1;
                mma_f16(oacc[j], ap, bv[g][p * 2], bv[g][p * 2 + 1]);
            }
        }
        if (kt + 2 < 16) issueKV(kt + 2);
    }

    #pragma unroll
    for (int h = 0; h < 2; h++) {
        lsum[h] += __shfl_xor_sync(0xffffffffu, lsum[h], 1);
        lsum[h] += __shfl_xor_sync(0xffffffffu, lsum[h], 2);
    }
    if ((lane & 3) == 0) {
        linv[wid * 16 + (lane >> 2)]     = 1.f / lsum[0];
        linv[wid * 16 + (lane >> 2) + 8] = 1.f / lsum[1];
    }
    __syncthreads();
    float* ow = (float*)sm_ + wid * 16 * 66;
    #pragma unroll
    for (int j = 0; j < 8; j++) {
        int c = j * 8 + (lane & 3) * 2;
        int r = lane >> 2;
        ow[r * 66 + c]           = oacc[j][0];
        ow[r * 66 + c + 1]       = oacc[j][1];
        ow[(r + 8) * 66 + c]     = oacc[j][2];
        ow[(r + 8) * 66 + c + 1] = oacc[j][3];
    }
    __syncwarp();
    for (int i = lane; i < 256; i += 32) {
        int r = i >> 4, cg = (i & 15) * 4;
        float inv = linv[wid * 16 + r];
        uint2 u;
        u.x = pack2h(ow[r * 66 + cg] * inv,     ow[r * 66 + cg + 1] * inv);
        u.y = pack2h(ow[r * 66 + cg + 2] * inv, ow[r * 66 + cg + 3] * inv);
        size_t go = ((size_t)bb * 1024 + qb * 128 + wid * 16 + r) * 512 + hh * 64 + cg;
        *(uint2*)(o_g + go) = u;
    }
}

// ---------------------------------------------------------------------------
// Launcher
// ---------------------------------------------------------------------------
extern "C" void kernel_launch(void* const* d_in, const int* in_sizes, int n_in,
                              void* d_out, int out_size)
{
    const float* x      = (const float*)d_in[0];
    const float* qkv_w  = (const float*)d_in[1];
    const float* proj_w = (const float*)d_in[2];
    const float* proj_b = (const float*)d_in[3];
    const float* mlp_w1 = (const float*)d_in[4];
    const float* mlp_b1 = (const float*)d_in[5];
    const float* mlp_w2 = (const float*)d_in[6];
    const float* mlp_b2 = (const float*)d_in[7];
    const float* n1g    = (const float*)d_in[8];
    const float* n1b    = (const float*)d_in[9];
    const float* n2g    = (const float*)d_in[10];
    const float* n2b    = (const float*)d_in[11];
    const float* btab   = (const float*)d_in[12];
    float* out = (float*)d_out;

    float* x1;
    cudaGetSymbolAddress((void**)&x1, d_x1);
    __half *h_, *o_, *hid, *qkv, *wq, *wp, *w1, *w2;
    cudaGetSymbolAddress((void**)&h_,  g_h);
    cudaGetSymbolAddress((void**)&o_,  g_o);
    cudaGetSymbolAddress((void**)&hid, g_hid);
    cudaGetSymbolAddress((void**)&qkv, g_qkv);
    cudaGetSymbolAddress((void**)&wq,  g_wqkv);
    cudaGetSymbolAddress((void**)&wp,  g_wprj);
    cudaGetSymbolAddress((void**)&w1,  g_w1);
    cudaGetSymbolAddress((void**)&w2,  g_w2);

    cudaFuncSetAttribute(attn_tc_kernel,
        cudaFuncAttributeMaxDynamicSharedMemorySize, ATTN_SMEM);
    cudaFuncSetAttribute(mma_gemm<512, EPI_QKV>,
        cudaFuncAttributeMaxDynamicSharedMemorySize, GEMM_SMEM);
    cudaFuncSetAttribute(mma_gemm<512, EPI_PROJ>,
        cudaFuncAttributeMaxDynamicSharedMemorySize, GEMM_SMEM);
    cudaFuncSetAttribute(mma_gemm<512, EPI_GELU>,
        cudaFuncAttributeMaxDynamicSharedMemorySize, GEMM_SMEM);
    cudaFuncSetAttribute(mma_gemm<2048, EPI_OUT>,
        cudaFuncAttributeMaxDynamicSharedMemorySize, GEMM_SMEM);

    cvt4_kernel<<<3072, 256>>>(qkv_w, wq, proj_w, wp, mlp_w1, w1, mlp_w2, w2);

    // LN1 (2 rows per block)
    ln_h_kernel<<<MROWS / 2, 256>>>(x, n1g, n1b, h_);
    // QKV (N=1536) -> [m][1536], q pre-scaled by 0.125*log2e
    mma_gemm<512, EPI_QKV><<<dim3(12, 256), 256, GEMM_SMEM>>>(
        h_, wq, nullptr, nullptr, nullptr, qkv, 1536);
    // attention
    attn_tc_kernel<<<dim3(8, 256), 256, ATTN_SMEM>>>(qkv, btab, o_);
    // proj + residual (N=512)
    mma_gemm<512, EPI_PROJ><<<dim3(4, 256), 256, GEMM_SMEM>>>(
        o_, wp, proj_b, x, x1, nullptr, 512);
    // LN2 (2 rows per block)
    ln_h_kernel<<<MROWS / 2, 256>>>(x1, n2g, n2b, h_);
    // MLP1 + GELU (N=2048)
    mma_gemm<512, EPI_GELU><<<dim3(16, 256), 256, GEMM_SMEM>>>(
        h_, w1, mlp_b1, nullptr, nullptr, hid, 2048);
    // MLP2 + residual -> out (N=512, K=2048)
    mma_gemm<2048, EPI_OUT><<<dim3(4, 256), 256, GEMM_SMEM>>>(
        hid, w2, mlp_b2, x1, out, nullptr, 512);
}